// round 3
// baseline (speedup 1.0000x reference)
#include <cuda_runtime.h>
#include <math.h>

// Problem constants (fixed by the dataset)
#define NN      50000
#define NE      800000
#define ND      128
#define ED      32
#define CATD    288     // 2*ND + ED
#define GD      384     // 3*ND
#define NROUNDS 2

#define SCAN_BLK 1024
#define NSCANBLK ((NN + SCAN_BLK - 1) / SCAN_BLK)   // 49

// ---------------- device scratch (module-scope, no allocations) -------------
__device__ int   g_cnt[NN];
__device__ int   g_rowptr[NN + 1];
__device__ int   g_cursor[NN];
__device__ float g_degf[NN];
__device__ int   g_bsum[64];
__device__ int   g_boffs[64];
__device__ int   g_eidx[NE];
__device__ float g_X[(size_t)NN * CATD];
__device__ float g_a[(size_t)NN * ND];
__device__ float g_gi[(size_t)NN * GD];
__device__ float g_gh[(size_t)NN * GD];

// ---------------- utility kernels -------------------------------------------
__global__ void copy_f32(const float* __restrict__ src, float* __restrict__ dst, int n) {
    int i = blockIdx.x * blockDim.x + threadIdx.x;
    if (i < n) dst[i] = src[i];
}

__global__ void zero_cnt() {
    int i = blockIdx.x * blockDim.x + threadIdx.x;
    if (i < NN) g_cnt[i] = 0;
}

__global__ void count_kernel(const int* __restrict__ dst) {
    int e = blockIdx.x * blockDim.x + threadIdx.x;
    if (e < NE) atomicAdd(&g_cnt[dst[e]], 1);
}

// inclusive block scan of g_cnt; partial results into g_rowptr[1+i], block sums to g_bsum
__global__ void scan1() {
    __shared__ int buf[SCAN_BLK];
    int tid = threadIdx.x;
    int i = blockIdx.x * SCAN_BLK + tid;
    buf[tid] = (i < NN) ? g_cnt[i] : 0;
    __syncthreads();
    #pragma unroll
    for (int off = 1; off < SCAN_BLK; off <<= 1) {
        int t = (tid >= off) ? buf[tid - off] : 0;
        __syncthreads();
        buf[tid] += t;
        __syncthreads();
    }
    if (i < NN) g_rowptr[1 + i] = buf[tid];
    if (tid == SCAN_BLK - 1) g_bsum[blockIdx.x] = buf[tid];
}

// scan of the 49 block sums -> exclusive offsets
__global__ void scan2() {
    __shared__ int buf[64];
    int tid = threadIdx.x;
    int own = (tid < NSCANBLK) ? g_bsum[tid] : 0;
    buf[tid] = own;
    __syncthreads();
    #pragma unroll
    for (int off = 1; off < 64; off <<= 1) {
        int t = (tid >= off) ? buf[tid - off] : 0;
        __syncthreads();
        buf[tid] += t;
        __syncthreads();
    }
    if (tid < NSCANBLK) g_boffs[tid] = buf[tid] - own;  // exclusive
}

// finalize rowptr, cursor, degf
__global__ void scan3() {
    int i = blockIdx.x * blockDim.x + threadIdx.x;
    if (i >= NN) return;
    int b = i / SCAN_BLK;
    int incl = g_rowptr[1 + i] + g_boffs[b];
    g_rowptr[1 + i] = incl;
    int c = g_cnt[i];
    g_cursor[i] = incl - c;
    g_degf[i]   = (float)c;
    if (i == 0) g_rowptr[0] = 0;
}

__global__ void fill_kernel(const int* __restrict__ dst) {
    int e = blockIdx.x * blockDim.x + threadIdx.x;
    if (e < NE) {
        int d = dst[e];
        int p = atomicAdd(&g_cursor[d], 1);
        g_eidx[p] = e;
    }
}

// ---------------- per-round gather: builds X = [S | deg*hv | E] --------------
__global__ void gather_kernel(const float* __restrict__ hv, const float* __restrict__ he,
                              const int* __restrict__ src) {
    int warp = (blockIdx.x * blockDim.x + threadIdx.x) >> 5;
    int lane = threadIdx.x & 31;
    if (warp >= NN) return;
    int v = warp;
    int beg = g_rowptr[v];
    int end = g_rowptr[v + 1];
    float s0 = 0.f, s1 = 0.f, s2 = 0.f, s3 = 0.f, se = 0.f;
    for (int i = beg; i < end; i++) {
        int e = g_eidx[i];
        int s = src[e];
        const float* hr = hv + (size_t)s * ND;
        s0 += hr[lane];
        s1 += hr[32 + lane];
        s2 += hr[64 + lane];
        s3 += hr[96 + lane];
        se += he[(size_t)e * ED + lane];
    }
    float d = g_degf[v];
    float* xr = g_X + (size_t)v * CATD;
    xr[lane]       = s0;
    xr[32 + lane]  = s1;
    xr[64 + lane]  = s2;
    xr[96 + lane]  = s3;
    const float* hvr = hv + (size_t)v * ND;
    xr[128 + lane] = d * hvr[lane];
    xr[160 + lane] = d * hvr[32 + lane];
    xr[192 + lane] = d * hvr[64 + lane];
    xr[224 + lane] = d * hvr[96 + lane];
    xr[256 + lane] = se;
}

// ---------------- fp32 tiled GEMM: C = A@W + rowscale*bias -------------------
// BM=BN=128, BK=16, 256 threads, 8x8 register tile.
// Requires K % 16 == 0 and N % 128 == 0 (holds: K in {288,128}, N in {128,384}).
#define BM 128
#define BN 128
#define BK 16
#define TM 8
#define TN 8

__global__ __launch_bounds__(256)
void gemm_bias(const float* __restrict__ A, const float* __restrict__ W,
               const float* __restrict__ bias, const float* __restrict__ rowscale,
               float* __restrict__ C, int M, int K, int N) {
    __shared__ float sA[BK][BM + 4];
    __shared__ float sW[BK][BN];
    int tid = threadIdx.x;
    int tx = tid & 15;          // 0..15 -> output cols tx*8..tx*8+7
    int ty = tid >> 4;          // 0..15 -> output rows ty*8..ty*8+7
    int blockRow = blockIdx.y * BM;
    int blockCol = blockIdx.x * BN;

    // A tile load mapping: (row = tid/4 in 0..63, 2 passes) x (float4 at (tid%4)*4)
    int arow = tid >> 2;
    int ac4  = (tid & 3) * 4;
    // W tile load mapping: (krow = tid/32 in 0..7, 2 passes) x (float4 at (tid%32)*4)
    int wrow = tid >> 5;
    int wc4  = (tid & 31) * 4;

    float acc[TM][TN];
    #pragma unroll
    for (int i = 0; i < TM; i++)
        #pragma unroll
        for (int j = 0; j < TN; j++) acc[i][j] = 0.f;

    for (int k0 = 0; k0 < K; k0 += BK) {
        #pragma unroll
        for (int p = 0; p < 2; p++) {
            int r = arow + p * 64;
            int grow = blockRow + r;
            float4 v = make_float4(0.f, 0.f, 0.f, 0.f);
            if (grow < M) v = *(const float4*)(A + (size_t)grow * K + k0 + ac4);
            sA[ac4 + 0][r] = v.x;
            sA[ac4 + 1][r] = v.y;
            sA[ac4 + 2][r] = v.z;
            sA[ac4 + 3][r] = v.w;
        }
        #pragma unroll
        for (int p = 0; p < 2; p++) {
            int r = wrow + p * 8;
            float4 v = *(const float4*)(W + (size_t)(k0 + r) * N + blockCol + wc4);
            *(float4*)(&sW[r][wc4]) = v;
        }
        __syncthreads();
        #pragma unroll
        for (int k = 0; k < BK; k++) {
            float a0[TM], b0[TN];
            #pragma unroll
            for (int i = 0; i < TM; i++) a0[i] = sA[k][ty * TM + i];
            #pragma unroll
            for (int j = 0; j < TN; j++) b0[j] = sW[k][tx * TN + j];
            #pragma unroll
            for (int i = 0; i < TM; i++)
                #pragma unroll
                for (int j = 0; j < TN; j++) acc[i][j] += a0[i] * b0[j];
        }
        __syncthreads();
    }

    #pragma unroll
    for (int i = 0; i < TM; i++) {
        int grow = blockRow + ty * TM + i;
        if (grow >= M) break;
        float rs = rowscale ? rowscale[grow] : 1.0f;
        float* crow = C + (size_t)grow * N + blockCol + tx * TN;
        #pragma unroll
        for (int j = 0; j < TN; j += 4) {
            int gc = blockCol + tx * TN + j;
            float4 o;
            o.x = acc[i][j + 0] + (bias ? rs * bias[gc + 0] : 0.f);
            o.y = acc[i][j + 1] + (bias ? rs * bias[gc + 1] : 0.f);
            o.z = acc[i][j + 2] + (bias ? rs * bias[gc + 2] : 0.f);
            o.w = acc[i][j + 3] + (bias ? rs * bias[gc + 3] : 0.f);
            *(float4*)(crow + j) = o;
        }
    }
}

// ---------------- GRU elementwise --------------------------------------------
__global__ void gru_kernel(float* __restrict__ hv) {
    int idx = blockIdx.x * blockDim.x + threadIdx.x;
    if (idx >= NN * ND) return;
    int v = idx / ND;
    int j = idx - v * ND;
    const float* gi = g_gi + (size_t)v * GD;
    const float* gh = g_gh + (size_t)v * GD;
    float ir = gi[j],        hr = gh[j];
    float iz = gi[128 + j],  hz = gh[128 + j];
    float in_ = gi[256 + j], hn = gh[256 + j];
    float r = 1.0f / (1.0f + expf(-(ir + hr)));
    float z = 1.0f / (1.0f + expf(-(iz + hz)));
    float n = tanhf(in_ + r * hn);
    float h = hv[idx];
    hv[idx] = (1.0f - z) * n + z * h;
}

// ---------------- launch ------------------------------------------------------
extern "C" void kernel_launch(void* const* d_in, const int* in_sizes, int n_in,
                              void* d_out, int out_size) {
    const float* hv    = (const float*)d_in[0];
    const float* he    = (const float*)d_in[1];
    const int*   src   = (const int*)d_in[2];
    const int*   dst   = (const int*)d_in[3];
    const float* W_msg = (const float*)d_in[4];
    const float* b_msg = (const float*)d_in[5];
    const float* W_ih  = (const float*)d_in[6];
    const float* W_hh  = (const float*)d_in[7];
    const float* b_ih  = (const float*)d_in[8];
    const float* b_hh  = (const float*)d_in[9];
    float* H = (float*)d_out;   // hv state lives in d_out

    // init: copy hv into state buffer, zero histogram
    copy_f32<<<(NN * ND + 255) / 256, 256>>>(hv, H, NN * ND);
    zero_cnt<<<(NN + 255) / 256, 256>>>();

    // CSR build (topology fixed across rounds)
    count_kernel<<<(NE + 255) / 256, 256>>>(dst);
    scan1<<<NSCANBLK, SCAN_BLK>>>();
    scan2<<<1, 64>>>();
    scan3<<<(NN + 255) / 256, 256>>>();
    fill_kernel<<<(NE + 255) / 256, 256>>>(dst);

    dim3 gemm_grid_a(1, (NN + BM - 1) / BM);
    dim3 gemm_grid_g(GD / BN, (NN + BM - 1) / BM);

    for (int t = 0; t < NROUNDS; t++) {
        // X = [S | deg*hv | E]
        gather_kernel<<<(NN * 32 + 255) / 256, 256>>>(H, he, src);

        float* aptr;  cudaGetSymbolAddress((void**)&aptr,  g_a);
        float* xptr;  cudaGetSymbolAddress((void**)&xptr,  g_X);
        float* giptr; cudaGetSymbolAddress((void**)&giptr, g_gi);
        float* ghptr; cudaGetSymbolAddress((void**)&ghptr, g_gh);
        float* dptr;  cudaGetSymbolAddress((void**)&dptr,  g_degf);

        // a = X @ W_msg[t] + deg * b_msg[t]
        gemm_bias<<<gemm_grid_a, 256>>>(xptr, W_msg + (size_t)t * CATD * ND,
                                        b_msg + (size_t)t * ND, dptr,
                                        aptr, NN, CATD, ND);
        // gi = a @ W_ih[t] + b_ih[t]
        gemm_bias<<<gemm_grid_g, 256>>>(aptr, W_ih + (size_t)t * ND * GD,
                                        b_ih + (size_t)t * GD, (const float*)nullptr,
                                        giptr, NN, ND, GD);
        // gh = H @ W_hh[t] + b_hh[t]
        gemm_bias<<<gemm_grid_g, 256>>>(H, W_hh + (size_t)t * ND * GD,
                                        b_hh + (size_t)t * GD, (const float*)nullptr,
                                        ghptr, NN, ND, GD);
        // H = GRU(a-derived gates, H)
        gru_kernel<<<(NN * ND + 255) / 256, 256>>>(H);
    }
}

// round 8
// speedup vs baseline: 1.5349x; 1.5349x over previous
#include <cuda_runtime.h>
#include <cuda_bf16.h>
#include <math.h>
#include <stdint.h>

// Problem constants
#define NN      50000
#define NE      800000
#define ND      128
#define ED      32
#define CATD    288
#define KPAD    320     // CATD padded to multiple of 64
#define GD      384     // 3*ND
#define NROUNDS 2

#define SCAN_BLK 1024
#define NSCANBLK ((NN + SCAN_BLK - 1) / SCAN_BLK)   // 49

// ---------------- device scratch -------------------------------------------
__device__ int   g_cnt[NN];
__device__ int   g_rowptr[NN + 1];
__device__ int   g_cursor[NN];
__device__ float g_degf[NN];
__device__ int   g_bsum[64];
__device__ int   g_boffs[64];
__device__ int   g_eidx[NE];

__device__ __nv_bfloat16 g_Xh[(size_t)NN * KPAD];
__device__ __nv_bfloat16 g_Xl[(size_t)NN * KPAD];
__device__ __nv_bfloat16 g_ah[(size_t)NN * ND];
__device__ __nv_bfloat16 g_al[(size_t)NN * ND];
__device__ __nv_bfloat16 g_Hh[(size_t)NN * ND];
__device__ __nv_bfloat16 g_Hl[(size_t)NN * ND];
__device__ float g_gi[(size_t)NN * GD];
__device__ float g_gh[(size_t)NN * GD];

// transposed + split weights (per round, reused)
__device__ __nv_bfloat16 g_Bmsg_h[ND * KPAD];
__device__ __nv_bfloat16 g_Bmsg_l[ND * KPAD];
__device__ __nv_bfloat16 g_Bih_h[GD * ND];
__device__ __nv_bfloat16 g_Bih_l[GD * ND];
__device__ __nv_bfloat16 g_Bhh_h[GD * ND];
__device__ __nv_bfloat16 g_Bhh_l[GD * ND];

// ---------------- small helpers --------------------------------------------
__device__ __forceinline__ void split2(float x, __nv_bfloat16& h, __nv_bfloat16& l) {
    h = __float2bfloat16(x);
    l = __float2bfloat16(x - __bfloat162float(h));
}

__device__ __forceinline__ uint32_t smem_u32(const void* p) {
    uint32_t a;
    asm("{ .reg .u64 t; cvta.to.shared.u64 t, %1; cvt.u32.u64 %0, t; }" : "=r"(a) : "l"(p));
    return a;
}

__device__ __forceinline__ void ldm_x4(uint32_t* r, uint32_t addr) {
    asm volatile("ldmatrix.sync.aligned.m8n8.x4.shared.b16 {%0,%1,%2,%3}, [%4];"
        : "=r"(r[0]), "=r"(r[1]), "=r"(r[2]), "=r"(r[3]) : "r"(addr));
}

__device__ __forceinline__ void mma_bf16(float* c, const uint32_t* a, const uint32_t* b) {
    asm volatile(
        "mma.sync.aligned.m16n8k16.row.col.f32.bf16.bf16.f32 "
        "{%0,%1,%2,%3}, {%4,%5,%6,%7}, {%8,%9}, {%0,%1,%2,%3};"
        : "+f"(c[0]), "+f"(c[1]), "+f"(c[2]), "+f"(c[3])
        : "r"(a[0]), "r"(a[1]), "r"(a[2]), "r"(a[3]), "r"(b[0]), "r"(b[1]));
}

// ---------------- init / CSR kernels ----------------------------------------
__global__ void copy_split_kernel(const float* __restrict__ src, float* __restrict__ dst,
                                  __nv_bfloat16* __restrict__ dh, __nv_bfloat16* __restrict__ dl,
                                  int n) {
    int i = blockIdx.x * blockDim.x + threadIdx.x;
    if (i < n) {
        float v = src[i];
        dst[i] = v;
        split2(v, dh[i], dl[i]);
    }
}

__global__ void zero_cnt() {
    int i = blockIdx.x * blockDim.x + threadIdx.x;
    if (i < NN) g_cnt[i] = 0;
}

__global__ void count_kernel(const int* __restrict__ dst) {
    int e = blockIdx.x * blockDim.x + threadIdx.x;
    if (e < NE) atomicAdd(&g_cnt[dst[e]], 1);
}

__global__ void scan1() {
    __shared__ int buf[SCAN_BLK];
    int tid = threadIdx.x;
    int i = blockIdx.x * SCAN_BLK + tid;
    buf[tid] = (i < NN) ? g_cnt[i] : 0;
    __syncthreads();
    #pragma unroll
    for (int off = 1; off < SCAN_BLK; off <<= 1) {
        int t = (tid >= off) ? buf[tid - off] : 0;
        __syncthreads();
        buf[tid] += t;
        __syncthreads();
    }
    if (i < NN) g_rowptr[1 + i] = buf[tid];
    if (tid == SCAN_BLK - 1) g_bsum[blockIdx.x] = buf[tid];
}

__global__ void scan2() {
    __shared__ int buf[64];
    int tid = threadIdx.x;
    int own = (tid < NSCANBLK) ? g_bsum[tid] : 0;
    buf[tid] = own;
    __syncthreads();
    #pragma unroll
    for (int off = 1; off < 64; off <<= 1) {
        int t = (tid >= off) ? buf[tid - off] : 0;
        __syncthreads();
        buf[tid] += t;
        __syncthreads();
    }
    if (tid < NSCANBLK) g_boffs[tid] = buf[tid] - own;
}

__global__ void scan3() {
    int i = blockIdx.x * blockDim.x + threadIdx.x;
    if (i >= NN) return;
    int b = i / SCAN_BLK;
    int incl = g_rowptr[1 + i] + g_boffs[b];
    g_rowptr[1 + i] = incl;
    int c = g_cnt[i];
    g_cursor[i] = incl - c;
    g_degf[i]   = (float)c;
    if (i == 0) g_rowptr[0] = 0;
}

__global__ void fill_kernel(const int* __restrict__ dst) {
    int e = blockIdx.x * blockDim.x + threadIdx.x;
    if (e < NE) {
        int d = dst[e];
        int p = atomicAdd(&g_cursor[d], 1);
        g_eidx[p] = e;
    }
}

// ---------------- weight transpose + split ----------------------------------
__global__ void conv_wmsg(const float* __restrict__ W) {
    int idx = blockIdx.x * blockDim.x + threadIdx.x;
    if (idx >= ND * KPAD) return;
    int n = idx / KPAD;
    int k = idx - n * KPAD;
    float v = (k < CATD) ? W[(size_t)k * ND + n] : 0.0f;
    split2(v, g_Bmsg_h[idx], g_Bmsg_l[idx]);
}

__global__ void conv_wg(const float* __restrict__ W, __nv_bfloat16* __restrict__ bh,
                        __nv_bfloat16* __restrict__ bl) {
    int idx = blockIdx.x * blockDim.x + threadIdx.x;
    if (idx >= GD * ND) return;
    int n = idx / ND;
    int k = idx - n * ND;
    float v = W[(size_t)k * GD + n];
    split2(v, bh[idx], bl[idx]);
}

// ---------------- gather: X = [S | deg*hv | E | 0pad] as bf16 splits ---------
__global__ void gather_kernel(const float* __restrict__ hv, const float* __restrict__ he,
                              const int* __restrict__ src) {
    int warp = (blockIdx.x * blockDim.x + threadIdx.x) >> 5;
    int lane = threadIdx.x & 31;
    if (warp >= NN) return;
    int v = warp;
    int beg = g_rowptr[v];
    int end = g_rowptr[v + 1];
    float s0 = 0.f, s1 = 0.f, s2 = 0.f, s3 = 0.f, se = 0.f;
    for (int i = beg; i < end; i++) {
        int e = g_eidx[i];
        int s = src[e];
        const float* hr = hv + (size_t)s * ND;
        s0 += hr[lane];
        s1 += hr[32 + lane];
        s2 += hr[64 + lane];
        s3 += hr[96 + lane];
        se += he[(size_t)e * ED + lane];
    }
    float d = g_degf[v];
    const float* hvr = hv + (size_t)v * ND;
    __nv_bfloat16* xh = g_Xh + (size_t)v * KPAD;
    __nv_bfloat16* xl = g_Xl + (size_t)v * KPAD;
    float vals[9];
    vals[0] = s0; vals[1] = s1; vals[2] = s2; vals[3] = s3;
    vals[4] = d * hvr[lane];
    vals[5] = d * hvr[32 + lane];
    vals[6] = d * hvr[64 + lane];
    vals[7] = d * hvr[96 + lane];
    vals[8] = se;
    #pragma unroll
    for (int s = 0; s < 9; s++)
        split2(vals[s], xh[s * 32 + lane], xl[s * 32 + lane]);
    xh[288 + lane] = __float2bfloat16(0.f);
    xl[288 + lane] = __float2bfloat16(0.f);
}

// ---------------- HMMA bf16-split GEMM ---------------------------------------
// C[M, N_total] = (Ah+Al)[M,K] @ (Bh+Bl)^T   (B stored [N_total][K], K-major)
//   + rowscale*bias.  128x128 CTA tile, 8 warps (64x32 each), K chunk = 64.
// 3 passes: AhBh + AhBl + AlBh, fp32 accumulate (eff. precision ~2^-17).
#define SMG_BIAS 0
#define SMG_AH   1024
#define SMG_AL   (1024 + 16384)
#define SMG_BH   (1024 + 2 * 16384)
#define SMG_BL   (1024 + 3 * 16384)
#define SMG_TOTAL (1024 + 4 * 16384)

__global__ __launch_bounds__(256, 2)
void gemm_hmma(const __nv_bfloat16* __restrict__ Ah, const __nv_bfloat16* __restrict__ Al,
               const __nv_bfloat16* __restrict__ Bh, const __nv_bfloat16* __restrict__ Bl,
               const float* __restrict__ bias, const float* __restrict__ rowscale,
               float* __restrict__ Cf, __nv_bfloat16* __restrict__ Chi,
               __nv_bfloat16* __restrict__ Clo,
               int M, int K, int N_total) {
    extern __shared__ char smem[];
    int tid = threadIdx.x, wid = tid >> 5, lane = tid & 31;
    int blockRow = blockIdx.y * 128;
    int blockCol = blockIdx.x * 128;
    int warpRow = (wid >> 2) * 64;   // 0 / 64
    int warpCol = (wid & 3) * 32;    // 0..96

    float* sBias = (float*)(smem + SMG_BIAS);
    if (tid < 128) sBias[tid] = bias[blockCol + tid];

    uint32_t sAH = smem_u32(smem + SMG_AH);
    uint32_t sAL = smem_u32(smem + SMG_AL);
    uint32_t sBH = smem_u32(smem + SMG_BH);
    uint32_t sBL = smem_u32(smem + SMG_BL);

    float acc[4][4][4];
    #pragma unroll
    for (int mt = 0; mt < 4; mt++)
        #pragma unroll
        for (int nt = 0; nt < 4; nt++)
            #pragma unroll
            for (int q = 0; q < 4; q++) acc[mt][nt][q] = 0.f;

    // ldmatrix lane addressing: row = base + (lane&15), byte half = (lane>>4)*16
    int lrow  = lane & 15;
    uint32_t lhalf = (uint32_t)((lane >> 4) * 16);
    uint32_t rm = (uint32_t)((lrow & 7) << 4);   // swizzle XOR mask (row bits 0-2 -> bits 4-6)

    for (int k0 = 0; k0 < K; k0 += 64) {
        // ---- load 4 tiles of [128 rows x 64 bf16] (128B rows, SW128 swizzle) ----
        #pragma unroll
        for (int i = 0; i < 4; i++) {
            int linear = i * 256 + tid;
            int r  = linear >> 3;
            int cb = (linear & 7) * 16;
            int off = r * 128 + cb;
            int sw = off ^ ((off >> 3) & 0x70);
            int gr = blockRow + r;
            uint4 vh = make_uint4(0, 0, 0, 0), vl = make_uint4(0, 0, 0, 0);
            if (gr < M) {
                vh = *(const uint4*)((const char*)(Ah + (size_t)gr * K + k0) + cb);
                vl = *(const uint4*)((const char*)(Al + (size_t)gr * K + k0) + cb);
            }
            *(uint4*)(smem + SMG_AH + sw) = vh;
            *(uint4*)(smem + SMG_AL + sw) = vl;
            int gn = blockCol + r;  // always < N_total
            *(uint4*)(smem + SMG_BH + sw) =
                *(const uint4*)((const char*)(Bh + (size_t)gn * K + k0) + cb);
            *(uint4*)(smem + SMG_BL + sw) =
                *(const uint4*)((const char*)(Bl + (size_t)gn * K + k0) + cb);
        }
        __syncthreads();

        #pragma unroll
        for (int ks = 0; ks < 4; ks++) {
            uint32_t koff = ((uint32_t)(ks * 32) + lhalf) ^ rm;
            // B fragments for 4 n-tiles (two x4 groups of 16 n-rows each)
            uint32_t bfh[4][2], bfl[4][2];
            #pragma unroll
            for (int ng = 0; ng < 2; ng++) {
                uint32_t ro = (uint32_t)(warpCol + ng * 16 + lrow) * 128 + koff;
                uint32_t t[4];
                ldm_x4(t, sBH + ro);
                bfh[ng * 2 + 0][0] = t[0]; bfh[ng * 2 + 1][0] = t[1];
                bfh[ng * 2 + 0][1] = t[2]; bfh[ng * 2 + 1][1] = t[3];
                ldm_x4(t, sBL + ro);
                bfl[ng * 2 + 0][0] = t[0]; bfl[ng * 2 + 1][0] = t[1];
                bfl[ng * 2 + 0][1] = t[2]; bfl[ng * 2 + 1][1] = t[3];
            }
            #pragma unroll
            for (int mt = 0; mt < 4; mt++) {
                uint32_t ro = (uint32_t)(warpRow + mt * 16 + lrow) * 128 + koff;
                uint32_t ah[4], al[4];
                ldm_x4(ah, sAH + ro);
                ldm_x4(al, sAL + ro);
                #pragma unroll
                for (int nt = 0; nt < 4; nt++) {
                    mma_bf16(acc[mt][nt], ah, bfh[nt]);
                    mma_bf16(acc[mt][nt], ah, bfl[nt]);
                    mma_bf16(acc[mt][nt], al, bfh[nt]);
                }
            }
        }
        __syncthreads();
    }

    // ---- epilogue: registers -> gmem ----
    int rbase = blockRow + warpRow;
    #pragma unroll
    for (int mt = 0; mt < 4; mt++) {
        int r0 = rbase + mt * 16 + (lane >> 2);
        int r1 = r0 + 8;
        float rs0 = 1.f, rs1 = 1.f;
        if (rowscale) {
            if (r0 < M) rs0 = rowscale[r0];
            if (r1 < M) rs1 = rowscale[r1];
        }
        #pragma unroll
        for (int nt = 0; nt < 4; nt++) {
            int col = warpCol + nt * 8 + (lane & 3) * 2;
            float b0 = sBias[col], b1 = sBias[col + 1];
            int gcol = blockCol + col;
            float v00 = acc[mt][nt][0] + rs0 * b0;
            float v01 = acc[mt][nt][1] + rs0 * b1;
            float v10 = acc[mt][nt][2] + rs1 * b0;
            float v11 = acc[mt][nt][3] + rs1 * b1;
            if (Cf) {
                if (r0 < M) *(float2*)(Cf + (size_t)r0 * N_total + gcol) = make_float2(v00, v01);
                if (r1 < M) *(float2*)(Cf + (size_t)r1 * N_total + gcol) = make_float2(v10, v11);
            }
            if (Chi) {
                __nv_bfloat16 h0, l0, h1, l1;
                if (r0 < M) {
                    split2(v00, h0, l0); split2(v01, h1, l1);
                    *(unsigned*)(Chi + (size_t)r0 * N_total + gcol) =
                        ((unsigned)__bfloat16_as_ushort(h1) << 16) | __bfloat16_as_ushort(h0);
                    *(unsigned*)(Clo + (size_t)r0 * N_total + gcol) =
                        ((unsigned)__bfloat16_as_ushort(l1) << 16) | __bfloat16_as_ushort(l0);
                }
                if (r1 < M) {
                    split2(v10, h0, l0); split2(v11, h1, l1);
                    *(unsigned*)(Chi + (size_t)r1 * N_total + gcol) =
                        ((unsigned)__bfloat16_as_ushort(h1) << 16) | __bfloat16_as_ushort(h0);
                    *(unsigned*)(Clo + (size_t)r1 * N_total + gcol) =
                        ((unsigned)__bfloat16_as_ushort(l1) << 16) | __bfloat16_as_ushort(l0);
                }
            }
        }
    }
}

// ---------------- GRU elementwise (also emits H splits) ----------------------
__global__ void gru_kernel(float* __restrict__ hv, __nv_bfloat16* __restrict__ hh,
                           __nv_bfloat16* __restrict__ hl) {
    int idx = blockIdx.x * blockDim.x + threadIdx.x;
    if (idx >= NN * ND) return;
    int v = idx / ND;
    int j = idx - v * ND;
    const float* gi = g_gi + (size_t)v * GD;
    const float* gh = g_gh + (size_t)v * GD;
    float ir = gi[j],        hr = gh[j];
    float iz = gi[128 + j],  hz = gh[128 + j];
    float in_ = gi[256 + j], hn = gh[256 + j];
    float r = 1.0f / (1.0f + expf(-(ir + hr)));
    float z = 1.0f / (1.0f + expf(-(iz + hz)));
    float n = tanhf(in_ + r * hn);
    float h = hv[idx];
    float o = (1.0f - z) * n + z * h;
    hv[idx] = o;
    split2(o, hh[idx], hl[idx]);
}

// ---------------- launch -----------------------------------------------------
extern "C" void kernel_launch(void* const* d_in, const int* in_sizes, int n_in,
                              void* d_out, int out_size) {
    const float* hv    = (const float*)d_in[0];
    const float* he    = (const float*)d_in[1];
    const int*   src   = (const int*)d_in[2];
    const int*   dst   = (const int*)d_in[3];
    const float* W_msg = (const float*)d_in[4];
    const float* b_msg = (const float*)d_in[5];
    const float* W_ih  = (const float*)d_in[6];
    const float* W_hh  = (const float*)d_in[7];
    const float* b_ih  = (const float*)d_in[8];
    const float* b_hh  = (const float*)d_in[9];
    float* H = (float*)d_out;

    static int attr_done = 0;
    if (!attr_done) {
        cudaFuncSetAttribute(gemm_hmma, cudaFuncAttributeMaxDynamicSharedMemorySize, SMG_TOTAL);
        attr_done = 1;
    }

    __nv_bfloat16 *Xh, *Xl, *ah, *al, *Hh, *Hl;
    __nv_bfloat16 *Bmh, *Bml, *Bih_h, *Bih_l, *Bhh_h, *Bhh_l;
    float *giptr, *ghptr, *dptr;
    cudaGetSymbolAddress((void**)&Xh, g_Xh);
    cudaGetSymbolAddress((void**)&Xl, g_Xl);
    cudaGetSymbolAddress((void**)&ah, g_ah);
    cudaGetSymbolAddress((void**)&al, g_al);
    cudaGetSymbolAddress((void**)&Hh, g_Hh);
    cudaGetSymbolAddress((void**)&Hl, g_Hl);
    cudaGetSymbolAddress((void**)&Bmh, g_Bmsg_h);
    cudaGetSymbolAddress((void**)&Bml, g_Bmsg_l);
    cudaGetSymbolAddress((void**)&Bih_h, g_Bih_h);
    cudaGetSymbolAddress((void**)&Bih_l, g_Bih_l);
    cudaGetSymbolAddress((void**)&Bhh_h, g_Bhh_h);
    cudaGetSymbolAddress((void**)&Bhh_l, g_Bhh_l);
    cudaGetSymbolAddress((void**)&giptr, g_gi);
    cudaGetSymbolAddress((void**)&ghptr, g_gh);
    cudaGetSymbolAddress((void**)&dptr, g_degf);

    copy_split_kernel<<<(NN * ND + 255) / 256, 256>>>(hv, H, Hh, Hl, NN * ND);
    zero_cnt<<<(NN + 255) / 256, 256>>>();
    count_kernel<<<(NE + 255) / 256, 256>>>(dst);
    scan1<<<NSCANBLK, SCAN_BLK>>>();
    scan2<<<1, 64>>>();
    scan3<<<(NN + 255) / 256, 256>>>();
    fill_kernel<<<(NE + 255) / 256, 256>>>(dst);

    int mtiles = (NN + 127) / 128;   // 391

    for (int t = 0; t < NROUNDS; t++) {
        conv_wmsg<<<(ND * KPAD + 255) / 256, 256>>>(W_msg + (size_t)t * CATD * ND);
        conv_wg<<<(GD * ND + 255) / 256, 256>>>(W_ih + (size_t)t * ND * GD, Bih_h, Bih_l);
        conv_wg<<<(GD * ND + 255) / 256, 256>>>(W_hh + (size_t)t * ND * GD, Bhh_h, Bhh_l);

        gather_kernel<<<(NN * 32 + 255) / 256, 256>>>(H, he, src);

        // a = X @ Wmsg + deg * b_msg   (bf16-split output only)
        gemm_hmma<<<dim3(1, mtiles), 256, SMG_TOTAL>>>(
            Xh, Xl, Bmh, Bml, b_msg + (size_t)t * ND, dptr,
            (float*)nullptr, ah, al, NN, KPAD, ND);
        // gi = a @ W_ih + b_ih
        gemm_hmma<<<dim3(GD / 128, mtiles), 256, SMG_TOTAL>>>(
            ah, al, Bih_h, Bih_l, b_ih + (size_t)t * GD, (const float*)nullptr,
            giptr, (__nv_bfloat16*)nullptr, (__nv_bfloat16*)nullptr, NN, ND, GD);
        // gh = H @ W_hh + b_hh
        gemm_hmma<<<dim3(GD / 128, mtiles), 256, SMG_TOTAL>>>(
            Hh, Hl, Bhh_h, Bhh_l, b_hh + (size_t)t * GD, (const float*)nullptr,
            ghptr, (__nv_bfloat16*)nullptr, (__nv_bfloat16*)nullptr, NN, ND, GD);

        gru_kernel<<<(NN * ND + 255) / 256, 256>>>(H, Hh, Hl);
    }
}

// round 9
// speedup vs baseline: 1.6097x; 1.0488x over previous
#include <cuda_runtime.h>
#include <cuda_bf16.h>
#include <math.h>
#include <stdint.h>

// Problem constants
#define NN      50000
#define NE      800000
#define ND      128
#define ED      32
#define CATD    288
#define KPAD    320     // CATD padded to multiple of 32
#define GD      384     // 3*ND
#define NROUNDS 2

#define SCAN_BLK 1024
#define NSCANBLK ((NN + SCAN_BLK - 1) / SCAN_BLK)   // 49

// ---------------- device scratch -------------------------------------------
__device__ int   g_cnt[NN];
__device__ int   g_rowptr[NN + 1];
__device__ int   g_cursor[NN];
__device__ float g_degf[NN];
__device__ int   g_bsum[64];
__device__ int   g_boffs[64];
__device__ int   g_eidx[NE];

__device__ __nv_bfloat16 g_Xh[(size_t)NN * KPAD];
__device__ __nv_bfloat16 g_Xl[(size_t)NN * KPAD];
// cat = [a (cols 0-127) | H (cols 128-255)] bf16 hi/lo
__device__ __nv_bfloat16 g_cath[(size_t)NN * 256];
__device__ __nv_bfloat16 g_catl[(size_t)NN * 256];
__device__ float g_gsum[(size_t)NN * GD];
__device__ float g_hn[(size_t)NN * ND];

// weights (per round, rebuilt)
__device__ __nv_bfloat16 g_Bmsg_h[ND * KPAD];
__device__ __nv_bfloat16 g_Bmsg_l[ND * KPAD];
__device__ __nv_bfloat16 g_Bst_h[GD * 256];   // stacked [Wih;Whh] transposed
__device__ __nv_bfloat16 g_Bst_l[GD * 256];
__device__ __nv_bfloat16 g_Bwn_h[ND * ND];    // Whh_n transposed
__device__ __nv_bfloat16 g_Bwn_l[ND * ND];
__device__ float g_bsumv[GD];                 // b_ih + b_hh

// ---------------- small helpers --------------------------------------------
__device__ __forceinline__ void split2(float x, __nv_bfloat16& h, __nv_bfloat16& l) {
    h = __float2bfloat16(x);
    l = __float2bfloat16(x - __bfloat162float(h));
}

__device__ __forceinline__ uint32_t smem_u32(const void* p) {
    uint32_t a;
    asm("{ .reg .u64 t; cvta.to.shared.u64 t, %1; cvt.u32.u64 %0, t; }" : "=r"(a) : "l"(p));
    return a;
}

__device__ __forceinline__ void ldm_x4(uint32_t* r, uint32_t addr) {
    asm volatile("ldmatrix.sync.aligned.m8n8.x4.shared.b16 {%0,%1,%2,%3}, [%4];"
        : "=r"(r[0]), "=r"(r[1]), "=r"(r[2]), "=r"(r[3]) : "r"(addr));
}

__device__ __forceinline__ void mma_bf16(float* c, const uint32_t* a, const uint32_t* b) {
    asm volatile(
        "mma.sync.aligned.m16n8k16.row.col.f32.bf16.bf16.f32 "
        "{%0,%1,%2,%3}, {%4,%5,%6,%7}, {%8,%9}, {%0,%1,%2,%3};"
        : "+f"(c[0]), "+f"(c[1]), "+f"(c[2]), "+f"(c[3])
        : "r"(a[0]), "r"(a[1]), "r"(a[2]), "r"(a[3]), "r"(b[0]), "r"(b[1]));
}

__device__ __forceinline__ void cpasync16(uint32_t saddr, const void* gptr) {
    asm volatile("cp.async.cg.shared.global [%0], [%1], 16;"
                 :: "r"(saddr), "l"(gptr));
}

// ---------------- init / CSR kernels ----------------------------------------
__global__ void copy_split_kernel(const float* __restrict__ src, float* __restrict__ dst,
                                  int n) {
    int i = blockIdx.x * blockDim.x + threadIdx.x;
    if (i < n) {
        float v = src[i];
        dst[i] = v;
        int vv = i / ND, j = i - vv * ND;
        split2(v, g_cath[(size_t)vv * 256 + 128 + j], g_catl[(size_t)vv * 256 + 128 + j]);
    }
}

__global__ void zero_cnt() {
    int i = blockIdx.x * blockDim.x + threadIdx.x;
    if (i < NN) g_cnt[i] = 0;
}

__global__ void count_kernel(const int* __restrict__ dst) {
    int e = blockIdx.x * blockDim.x + threadIdx.x;
    if (e < NE) atomicAdd(&g_cnt[dst[e]], 1);
}

__global__ void scan1() {
    __shared__ int buf[SCAN_BLK];
    int tid = threadIdx.x;
    int i = blockIdx.x * SCAN_BLK + tid;
    buf[tid] = (i < NN) ? g_cnt[i] : 0;
    __syncthreads();
    #pragma unroll
    for (int off = 1; off < SCAN_BLK; off <<= 1) {
        int t = (tid >= off) ? buf[tid - off] : 0;
        __syncthreads();
        buf[tid] += t;
        __syncthreads();
    }
    if (i < NN) g_rowptr[1 + i] = buf[tid];
    if (tid == SCAN_BLK - 1) g_bsum[blockIdx.x] = buf[tid];
}

__global__ void scan2() {
    __shared__ int buf[64];
    int tid = threadIdx.x;
    int own = (tid < NSCANBLK) ? g_bsum[tid] : 0;
    buf[tid] = own;
    __syncthreads();
    #pragma unroll
    for (int off = 1; off < 64; off <<= 1) {
        int t = (tid >= off) ? buf[tid - off] : 0;
        __syncthreads();
        buf[tid] += t;
        __syncthreads();
    }
    if (tid < NSCANBLK) g_boffs[tid] = buf[tid] - own;
}

__global__ void scan3() {
    int i = blockIdx.x * blockDim.x + threadIdx.x;
    if (i >= NN) return;
    int b = i / SCAN_BLK;
    int incl = g_rowptr[1 + i] + g_boffs[b];
    g_rowptr[1 + i] = incl;
    int c = g_cnt[i];
    g_cursor[i] = incl - c;
    g_degf[i]   = (float)c;
    if (i == 0) g_rowptr[0] = 0;
}

__global__ void fill_kernel(const int* __restrict__ dst) {
    int e = blockIdx.x * blockDim.x + threadIdx.x;
    if (e < NE) {
        int d = dst[e];
        int p = atomicAdd(&g_cursor[d], 1);
        g_eidx[p] = e;
    }
}

// ---------------- weight transpose + split ----------------------------------
__global__ void conv_wmsg(const float* __restrict__ W) {
    int idx = blockIdx.x * blockDim.x + threadIdx.x;
    if (idx >= ND * KPAD) return;
    int n = idx / KPAD;
    int k = idx - n * KPAD;
    float v = (k < CATD) ? W[(size_t)k * ND + n] : 0.0f;
    split2(v, g_Bmsg_h[idx], g_Bmsg_l[idx]);
}

// stacked [Wih; Whh] -> [GD n][256 k], plus summed bias
__global__ void conv_stack(const float* __restrict__ Wih, const float* __restrict__ Whh,
                           const float* __restrict__ bih, const float* __restrict__ bhh) {
    int idx = blockIdx.x * blockDim.x + threadIdx.x;
    if (idx >= GD * 256) return;
    int n = idx >> 8;
    int k = idx & 255;
    float v = (k < 128) ? Wih[(size_t)k * GD + n] : Whh[(size_t)(k - 128) * GD + n];
    split2(v, g_Bst_h[idx], g_Bst_l[idx]);
    if (idx < GD) g_bsumv[idx] = bih[idx] + bhh[idx];
}

// Whh_n columns 256..383 -> [ND n][ND k]
__global__ void conv_whhn(const float* __restrict__ Whh) {
    int idx = blockIdx.x * blockDim.x + threadIdx.x;
    if (idx >= ND * ND) return;
    int n = idx >> 7;
    int k = idx & 127;
    float v = Whh[(size_t)k * GD + 256 + n];
    split2(v, g_Bwn_h[idx], g_Bwn_l[idx]);
}

// ---------------- gather: X = [S | deg*hv | E | 0pad] as bf16 splits ---------
__global__ void gather_kernel(const float* __restrict__ hv, const float* __restrict__ he,
                              const int* __restrict__ src) {
    int warp = (blockIdx.x * blockDim.x + threadIdx.x) >> 5;
    int lane = threadIdx.x & 31;
    if (warp >= NN) return;
    int v = warp;
    int beg = g_rowptr[v];
    int end = g_rowptr[v + 1];
    float s0 = 0.f, s1 = 0.f, s2 = 0.f, s3 = 0.f, se = 0.f;
    for (int i = beg; i < end; i++) {
        int e = g_eidx[i];
        int s = src[e];
        const float* hr = hv + (size_t)s * ND;
        s0 += hr[lane];
        s1 += hr[32 + lane];
        s2 += hr[64 + lane];
        s3 += hr[96 + lane];
        se += he[(size_t)e * ED + lane];
    }
    float d = g_degf[v];
    const float* hvr = hv + (size_t)v * ND;
    __nv_bfloat16* xh = g_Xh + (size_t)v * KPAD;
    __nv_bfloat16* xl = g_Xl + (size_t)v * KPAD;
    float vals[9];
    vals[0] = s0; vals[1] = s1; vals[2] = s2; vals[3] = s3;
    vals[4] = d * hvr[lane];
    vals[5] = d * hvr[32 + lane];
    vals[6] = d * hvr[64 + lane];
    vals[7] = d * hvr[96 + lane];
    vals[8] = se;
    #pragma unroll
    for (int s = 0; s < 9; s++)
        split2(vals[s], xh[s * 32 + lane], xl[s * 32 + lane]);
    xh[288 + lane] = __float2bfloat16(0.f);
    xl[288 + lane] = __float2bfloat16(0.f);
}

// ---------------- cp.async double-buffered HMMA bf16-split GEMM --------------
// C[M, Ncols] = (Ah+Al)[M,K] @ (Bh+Bl)^T   (B stored [Ncols][K], K-major)
//   + rowscale*bias.  128x128 CTA tile, 8 warps, K chunk 32, 2 smem stages.
// 3 passes: AhBh + AhBl + AlBh, fp32 accumulate.
#define KC 32
#define STG_BYTES 32768   // 4 tiles x 8KB per stage
#define SMG_BIAS  0
#define SMG_STAGE 1024
#define SMG_TOTAL (1024 + 2 * STG_BYTES)

__global__ __launch_bounds__(256, 2)
void gemm_hmma(const __nv_bfloat16* __restrict__ Ah, const __nv_bfloat16* __restrict__ Al,
               int lda,
               const __nv_bfloat16* __restrict__ Bh, const __nv_bfloat16* __restrict__ Bl,
               const float* __restrict__ bias, const float* __restrict__ rowscale,
               float* __restrict__ Cf, int ldcf,
               __nv_bfloat16* __restrict__ Chi, __nv_bfloat16* __restrict__ Clo, int ldch,
               int M, int K) {
    extern __shared__ char smem[];
    int tid = threadIdx.x, wid = tid >> 5, lane = tid & 31;
    int blockRow = blockIdx.y * 128;
    int blockCol = blockIdx.x * 128;
    int warpRow = (wid >> 2) * 64;   // 0 / 64
    int warpCol = (wid & 3) * 32;    // 0..96

    float* sBias = (float*)(smem + SMG_BIAS);
    if (tid < 128) sBias[tid] = bias[blockCol + tid];

    uint32_t sstage = smem_u32(smem + SMG_STAGE);

    float acc[4][4][4];
    #pragma unroll
    for (int mt = 0; mt < 4; mt++)
        #pragma unroll
        for (int nt = 0; nt < 4; nt++)
            #pragma unroll
            for (int q = 0; q < 4; q++) acc[mt][nt][q] = 0.f;

    // per-thread load mapping: 2 x 16B vecs per tile (128 rows x 64B rows)
    int l0 = tid, l1 = 256 + tid;
    int r0l = l0 >> 2, c0 = (l0 & 3) * 16;
    int r1l = l1 >> 2, c1 = (l1 & 3) * 16;
    int sw0 = (r0l * 64 + c0) ^ (((r0l * 64 + c0) >> 3) & 0x30);
    int sw1 = (r1l * 64 + c1) ^ (((r1l * 64 + c1) >> 3) & 0x30);
    int ga0 = blockRow + r0l; if (ga0 >= M) ga0 = M - 1;
    int ga1 = blockRow + r1l; if (ga1 >= M) ga1 = M - 1;
    int gb0 = blockCol + r0l;
    int gb1 = blockCol + r1l;

    int nchunks = K / KC;

    // prologue: prefetch chunk 0 into stage 0
    {
        int k0 = 0;
        uint32_t st = sstage;
        cpasync16(st + sw0,          (const char*)(Ah + (size_t)ga0 * lda + k0) + c0);
        cpasync16(st + sw1,          (const char*)(Ah + (size_t)ga1 * lda + k0) + c1);
        cpasync16(st + 8192 + sw0,   (const char*)(Al + (size_t)ga0 * lda + k0) + c0);
        cpasync16(st + 8192 + sw1,   (const char*)(Al + (size_t)ga1 * lda + k0) + c1);
        cpasync16(st + 16384 + sw0,  (const char*)(Bh + (size_t)gb0 * K + k0) + c0);
        cpasync16(st + 16384 + sw1,  (const char*)(Bh + (size_t)gb1 * K + k0) + c1);
        cpasync16(st + 24576 + sw0,  (const char*)(Bl + (size_t)gb0 * K + k0) + c0);
        cpasync16(st + 24576 + sw1,  (const char*)(Bl + (size_t)gb1 * K + k0) + c1);
    }
    asm volatile("cp.async.commit_group;" ::: "memory");

    int lrow  = lane & 15;
    uint32_t lhalf = (uint32_t)((lane >> 4) * 16);
    uint32_t rm = (uint32_t)(((lrow >> 1) & 3) << 4);  // 64B-row swizzle mask

    for (int kc = 0; kc < nchunks; kc++) {
        if (kc + 1 < nchunks) {
            int k0 = (kc + 1) * KC;
            uint32_t st = sstage + ((kc + 1) & 1) * STG_BYTES;
            cpasync16(st + sw0,          (const char*)(Ah + (size_t)ga0 * lda + k0) + c0);
            cpasync16(st + sw1,          (const char*)(Ah + (size_t)ga1 * lda + k0) + c1);
            cpasync16(st + 8192 + sw0,   (const char*)(Al + (size_t)ga0 * lda + k0) + c0);
            cpasync16(st + 8192 + sw1,   (const char*)(Al + (size_t)ga1 * lda + k0) + c1);
            cpasync16(st + 16384 + sw0,  (const char*)(Bh + (size_t)gb0 * K + k0) + c0);
            cpasync16(st + 16384 + sw1,  (const char*)(Bh + (size_t)gb1 * K + k0) + c1);
            cpasync16(st + 24576 + sw0,  (const char*)(Bl + (size_t)gb0 * K + k0) + c0);
            cpasync16(st + 24576 + sw1,  (const char*)(Bl + (size_t)gb1 * K + k0) + c1);
        }
        asm volatile("cp.async.commit_group;" ::: "memory");
        asm volatile("cp.async.wait_group 1;" ::: "memory");
        __syncthreads();

        uint32_t stb = sstage + (kc & 1) * STG_BYTES;
        uint32_t sAH = stb, sAL = stb + 8192, sBH = stb + 16384, sBL = stb + 24576;

        #pragma unroll
        for (int ks = 0; ks < 2; ks++) {
            uint32_t koff = ((uint32_t)(ks * 32) + lhalf) ^ rm;
            uint32_t bfh[4][2], bfl[4][2];
            #pragma unroll
            for (int ng = 0; ng < 2; ng++) {
                uint32_t ro = (uint32_t)(warpCol + ng * 16 + lrow) * 64 + koff;
                uint32_t t[4];
                ldm_x4(t, sBH + ro);
                bfh[ng * 2 + 0][0] = t[0]; bfh[ng * 2 + 1][0] = t[1];
                bfh[ng * 2 + 0][1] = t[2]; bfh[ng * 2 + 1][1] = t[3];
                ldm_x4(t, sBL + ro);
                bfl[ng * 2 + 0][0] = t[0]; bfl[ng * 2 + 1][0] = t[1];
                bfl[ng * 2 + 0][1] = t[2]; bfl[ng * 2 + 1][1] = t[3];
            }
            #pragma unroll
            for (int mt = 0; mt < 4; mt++) {
                uint32_t ro = (uint32_t)(warpRow + mt * 16 + lrow) * 64 + koff;
                uint32_t ah[4], al[4];
                ldm_x4(ah, sAH + ro);
                ldm_x4(al, sAL + ro);
                #pragma unroll
                for (int nt = 0; nt < 4; nt++) {
                    mma_bf16(acc[mt][nt], ah, bfh[nt]);
                    mma_bf16(acc[mt][nt], ah, bfl[nt]);
                    mma_bf16(acc[mt][nt], al, bfh[nt]);
                }
            }
        }
        __syncthreads();
    }

    // ---- epilogue ----
    int rbase = blockRow + warpRow;
    #pragma unroll
    for (int mt = 0; mt < 4; mt++) {
        int r0 = rbase + mt * 16 + (lane >> 2);
        int r1 = r0 + 8;
        float rs0 = 1.f, rs1 = 1.f;
        if (rowscale) {
            if (r0 < M) rs0 = rowscale[r0];
            if (r1 < M) rs1 = rowscale[r1];
        }
        #pragma unroll
        for (int nt = 0; nt < 4; nt++) {
            int col = warpCol + nt * 8 + (lane & 3) * 2;
            float b0 = sBias[col], b1 = sBias[col + 1];
            int gcol = blockCol + col;
            float v00 = acc[mt][nt][0] + rs0 * b0;
            float v01 = acc[mt][nt][1] + rs0 * b1;
            float v10 = acc[mt][nt][2] + rs1 * b0;
            float v11 = acc[mt][nt][3] + rs1 * b1;
            if (Cf) {
                if (r0 < M) *(float2*)(Cf + (size_t)r0 * ldcf + gcol) = make_float2(v00, v01);
                if (r1 < M) *(float2*)(Cf + (size_t)r1 * ldcf + gcol) = make_float2(v10, v11);
            }
            if (Chi) {
                __nv_bfloat16 h0, l0x, h1, l1;
                if (r0 < M) {
                    split2(v00, h0, l0x); split2(v01, h1, l1);
                    *(unsigned*)(Chi + (size_t)r0 * ldch + gcol) =
                        ((unsigned)__bfloat16_as_ushort(h1) << 16) | __bfloat16_as_ushort(h0);
                    *(unsigned*)(Clo + (size_t)r0 * ldch + gcol) =
                        ((unsigned)__bfloat16_as_ushort(l1) << 16) | __bfloat16_as_ushort(l0x);
                }
                if (r1 < M) {
                    split2(v10, h0, l0x); split2(v11, h1, l1);
                    *(unsigned*)(Chi + (size_t)r1 * ldch + gcol) =
                        ((unsigned)__bfloat16_as_ushort(h1) << 16) | __bfloat16_as_ushort(h0);
                    *(unsigned*)(Clo + (size_t)r1 * ldch + gcol) =
                        ((unsigned)__bfloat16_as_ushort(l1) << 16) | __bfloat16_as_ushort(l0x);
                }
            }
        }
    }
}

// ---------------- GRU elementwise: from gsum & hn ----------------------------
// gsum = a@Wih + H@Whh + b_ih + b_hh   (all 3 gates summed)
// hn   = H@Whh_n + b_hh_n
// r = sig(gsum_r); z = sig(gsum_z); in_ = gsum_n - hn; n = tanh(in_ + r*hn)
__global__ void gru_kernel(float* __restrict__ hv) {
    int idx = blockIdx.x * blockDim.x + threadIdx.x;
    if (idx >= NN * ND) return;
    int v = idx / ND;
    int j = idx - v * ND;
    const float* gs = g_gsum + (size_t)v * GD;
    float grz = gs[j];
    float gzz = gs[128 + j];
    float gnn = gs[256 + j];
    float hn = g_hn[(size_t)v * ND + j];
    float r = 1.0f / (1.0f + expf(-grz));
    float z = 1.0f / (1.0f + expf(-gzz));
    float in_ = gnn - hn;
    float n = tanhf(in_ + r * hn);
    float h = hv[idx];
    float o = (1.0f - z) * n + z * h;
    hv[idx] = o;
    split2(o, g_cath[(size_t)v * 256 + 128 + j], g_catl[(size_t)v * 256 + 128 + j]);
}

// ---------------- launch -----------------------------------------------------
extern "C" void kernel_launch(void* const* d_in, const int* in_sizes, int n_in,
                              void* d_out, int out_size) {
    const float* hv    = (const float*)d_in[0];
    const float* he    = (const float*)d_in[1];
    const int*   src   = (const int*)d_in[2];
    const int*   dst   = (const int*)d_in[3];
    const float* W_msg = (const float*)d_in[4];
    const float* b_msg = (const float*)d_in[5];
    const float* W_ih  = (const float*)d_in[6];
    const float* W_hh  = (const float*)d_in[7];
    const float* b_ih  = (const float*)d_in[8];
    const float* b_hh  = (const float*)d_in[9];
    float* H = (float*)d_out;

    static int attr_done = 0;
    if (!attr_done) {
        cudaFuncSetAttribute(gemm_hmma, cudaFuncAttributeMaxDynamicSharedMemorySize, SMG_TOTAL);
        attr_done = 1;
    }

    __nv_bfloat16 *Xh, *Xl, *cath, *catl;
    __nv_bfloat16 *Bmh, *Bml, *Bsth, *Bstl, *Bwnh, *Bwnl;
    float *gsumptr, *hnptr, *dptr, *bsumvptr;
    cudaGetSymbolAddress((void**)&Xh, g_Xh);
    cudaGetSymbolAddress((void**)&Xl, g_Xl);
    cudaGetSymbolAddress((void**)&cath, g_cath);
    cudaGetSymbolAddress((void**)&catl, g_catl);
    cudaGetSymbolAddress((void**)&Bmh, g_Bmsg_h);
    cudaGetSymbolAddress((void**)&Bml, g_Bmsg_l);
    cudaGetSymbolAddress((void**)&Bsth, g_Bst_h);
    cudaGetSymbolAddress((void**)&Bstl, g_Bst_l);
    cudaGetSymbolAddress((void**)&Bwnh, g_Bwn_h);
    cudaGetSymbolAddress((void**)&Bwnl, g_Bwn_l);
    cudaGetSymbolAddress((void**)&gsumptr, g_gsum);
    cudaGetSymbolAddress((void**)&hnptr, g_hn);
    cudaGetSymbolAddress((void**)&dptr, g_degf);
    cudaGetSymbolAddress((void**)&bsumvptr, g_bsumv);

    copy_split_kernel<<<(NN * ND + 255) / 256, 256>>>(hv, H, NN * ND);
    zero_cnt<<<(NN + 255) / 256, 256>>>();
    count_kernel<<<(NE + 255) / 256, 256>>>(dst);
    scan1<<<NSCANBLK, SCAN_BLK>>>();
    scan2<<<1, 64>>>();
    scan3<<<(NN + 255) / 256, 256>>>();
    fill_kernel<<<(NE + 255) / 256, 256>>>(dst);

    int mtiles = (NN + 127) / 128;   // 391

    for (int t = 0; t < NROUNDS; t++) {
        conv_wmsg<<<(ND * KPAD + 255) / 256, 256>>>(W_msg + (size_t)t * CATD * ND);
        conv_stack<<<(GD * 256 + 255) / 256, 256>>>(W_ih + (size_t)t * ND * GD,
                                                    W_hh + (size_t)t * ND * GD,
                                                    b_ih + (size_t)t * GD,
                                                    b_hh + (size_t)t * GD);
        conv_whhn<<<(ND * ND + 255) / 256, 256>>>(W_hh + (size_t)t * ND * GD);

        gather_kernel<<<(NN * 32 + 255) / 256, 256>>>(H, he, src);

        // a = X @ Wmsg + deg*b_msg  -> cat cols 0-127 (bf16 splits)
        gemm_hmma<<<dim3(1, mtiles), 256, SMG_TOTAL>>>(
            Xh, Xl, KPAD, Bmh, Bml, b_msg + (size_t)t * ND, dptr,
            (float*)nullptr, 0, cath, catl, 256, NN, KPAD);
        // gsum = [a|H] @ [Wih;Whh] + (b_ih+b_hh)
        gemm_hmma<<<dim3(GD / 128, mtiles), 256, SMG_TOTAL>>>(
            cath, catl, 256, Bsth, Bstl, bsumvptr, (const float*)nullptr,
            gsumptr, GD, (__nv_bfloat16*)nullptr, (__nv_bfloat16*)nullptr, 0, NN, 256);
        // hn = H @ Whh_n + b_hh_n
        gemm_hmma<<<dim3(1, mtiles), 256, SMG_TOTAL>>>(
            cath + 128, catl + 128, 256, Bwnh, Bwnl,
            b_hh + (size_t)t * GD + 256, (const float*)nullptr,
            hnptr, ND, (__nv_bfloat16*)nullptr, (__nv_bfloat16*)nullptr, 0, NN, ND);

        gru_kernel<<<(NN * ND + 255) / 256, 256>>>(H);
    }
}

// round 10
// speedup vs baseline: 1.7352x; 1.0779x over previous
#include <cuda_runtime.h>
#include <cuda_bf16.h>
#include <math.h>
#include <stdint.h>

// Problem constants
#define NN      50000
#define NE      800000
#define ND      128
#define ED      32
#define CATD    288     // = KPAD now (divisible by KC=32)
#define KPAD    288
#define GD      384     // 3*ND
#define NROUNDS 2

#define SCAN_BLK 1024
#define NSCANBLK ((NN + SCAN_BLK - 1) / SCAN_BLK)   // 49

// ---------------- device scratch -------------------------------------------
__device__ int   g_cnt[NN];
__device__ int   g_rowptr[NN + 1];
__device__ int   g_cursor[NN];
__device__ float g_degf[NN];
__device__ int   g_bsum[64];
__device__ int   g_boffs[64];
__device__ int   g_eidx[NE];
__device__ float g_E[(size_t)NN * ED];          // per-node edge-feature sum (round-invariant)

__device__ __nv_bfloat16 g_Xh[(size_t)NN * KPAD];
__device__ __nv_bfloat16 g_Xl[(size_t)NN * KPAD];
// cat = [a (cols 0-127) | H (cols 128-255)] bf16 hi/lo
__device__ __nv_bfloat16 g_cath[(size_t)NN * 256];
__device__ __nv_bfloat16 g_catl[(size_t)NN * 256];
__device__ float g_grz[(size_t)NN * 256];
__device__ float g_in[(size_t)NN * ND];
__device__ float g_hn[(size_t)NN * ND];

// weights (per round, rebuilt)
__device__ __nv_bfloat16 g_Bmsg_h[ND * KPAD];
__device__ __nv_bfloat16 g_Bmsg_l[ND * KPAD];
__device__ __nv_bfloat16 g_Brz_h[256 * 256];   // stacked [Wih;Whh] r,z gates, transposed
__device__ __nv_bfloat16 g_Brz_l[256 * 256];
__device__ __nv_bfloat16 g_Bin_h[ND * ND];     // Wih_n transposed
__device__ __nv_bfloat16 g_Bin_l[ND * ND];
__device__ __nv_bfloat16 g_Bwn_h[ND * ND];     // Whh_n transposed
__device__ __nv_bfloat16 g_Bwn_l[ND * ND];
__device__ float g_brz[256];                   // b_ih + b_hh (r,z gates)

// ---------------- small helpers --------------------------------------------
__device__ __forceinline__ void split2(float x, __nv_bfloat16& h, __nv_bfloat16& l) {
    h = __float2bfloat16(x);
    l = __float2bfloat16(x - __bfloat162float(h));
}

__device__ __forceinline__ uint32_t smem_u32(const void* p) {
    uint32_t a;
    asm("{ .reg .u64 t; cvta.to.shared.u64 t, %1; cvt.u32.u64 %0, t; }" : "=r"(a) : "l"(p));
    return a;
}

__device__ __forceinline__ void ldm_x4(uint32_t* r, uint32_t addr) {
    asm volatile("ldmatrix.sync.aligned.m8n8.x4.shared.b16 {%0,%1,%2,%3}, [%4];"
        : "=r"(r[0]), "=r"(r[1]), "=r"(r[2]), "=r"(r[3]) : "r"(addr));
}

__device__ __forceinline__ void mma_bf16(float* c, const uint32_t* a, const uint32_t* b) {
    asm volatile(
        "mma.sync.aligned.m16n8k16.row.col.f32.bf16.bf16.f32 "
        "{%0,%1,%2,%3}, {%4,%5,%6,%7}, {%8,%9}, {%0,%1,%2,%3};"
        : "+f"(c[0]), "+f"(c[1]), "+f"(c[2]), "+f"(c[3])
        : "r"(a[0]), "r"(a[1]), "r"(a[2]), "r"(a[3]), "r"(b[0]), "r"(b[1]));
}

__device__ __forceinline__ void cpasync16(uint32_t saddr, const void* gptr) {
    asm volatile("cp.async.cg.shared.global [%0], [%1], 16;"
                 :: "r"(saddr), "l"(gptr));
}

// ---------------- init / CSR kernels ----------------------------------------
__global__ void copy_split_kernel(const float* __restrict__ src, float* __restrict__ dst,
                                  int n) {
    int i = blockIdx.x * blockDim.x + threadIdx.x;
    if (i < n) {
        float v = src[i];
        dst[i] = v;
        int vv = i / ND, j = i - vv * ND;
        split2(v, g_cath[(size_t)vv * 256 + 128 + j], g_catl[(size_t)vv * 256 + 128 + j]);
    }
}

__global__ void zero_cnt() {
    int i = blockIdx.x * blockDim.x + threadIdx.x;
    if (i < NN) g_cnt[i] = 0;
}

__global__ void count_kernel(const int* __restrict__ dst) {
    int e = blockIdx.x * blockDim.x + threadIdx.x;
    if (e < NE) atomicAdd(&g_cnt[dst[e]], 1);
}

__global__ void scan1() {
    __shared__ int buf[SCAN_BLK];
    int tid = threadIdx.x;
    int i = blockIdx.x * SCAN_BLK + tid;
    buf[tid] = (i < NN) ? g_cnt[i] : 0;
    __syncthreads();
    #pragma unroll
    for (int off = 1; off < SCAN_BLK; off <<= 1) {
        int t = (tid >= off) ? buf[tid - off] : 0;
        __syncthreads();
        buf[tid] += t;
        __syncthreads();
    }
    if (i < NN) g_rowptr[1 + i] = buf[tid];
    if (tid == SCAN_BLK - 1) g_bsum[blockIdx.x] = buf[tid];
}

__global__ void scan2() {
    __shared__ int buf[64];
    int tid = threadIdx.x;
    int own = (tid < NSCANBLK) ? g_bsum[tid] : 0;
    buf[tid] = own;
    __syncthreads();
    #pragma unroll
    for (int off = 1; off < 64; off <<= 1) {
        int t = (tid >= off) ? buf[tid - off] : 0;
        __syncthreads();
        buf[tid] += t;
        __syncthreads();
    }
    if (tid < NSCANBLK) g_boffs[tid] = buf[tid] - own;
}

__global__ void scan3() {
    int i = blockIdx.x * blockDim.x + threadIdx.x;
    if (i >= NN) return;
    int b = i / SCAN_BLK;
    int incl = g_rowptr[1 + i] + g_boffs[b];
    g_rowptr[1 + i] = incl;
    int c = g_cnt[i];
    g_cursor[i] = incl - c;
    g_degf[i]   = (float)c;
    if (i == 0) g_rowptr[0] = 0;
}

__global__ void fill_kernel(const int* __restrict__ dst) {
    int e = blockIdx.x * blockDim.x + threadIdx.x;
    if (e < NE) {
        int d = dst[e];
        int p = atomicAdd(&g_cursor[d], 1);
        g_eidx[p] = e;
    }
}

// per-node edge-feature sum (once; invariant across rounds)
__global__ void esum_kernel(const float* __restrict__ he) {
    int warp = (blockIdx.x * blockDim.x + threadIdx.x) >> 5;
    int lane = threadIdx.x & 31;
    if (warp >= NN) return;
    int beg = g_rowptr[warp], end = g_rowptr[warp + 1];
    float se = 0.f;
    for (int i = beg; i < end; i++)
        se += he[(size_t)g_eidx[i] * ED + lane];
    g_E[(size_t)warp * ED + lane] = se;
}

// ---------------- weight transpose + split ----------------------------------
__global__ void conv_wmsg(const float* __restrict__ W) {
    int idx = blockIdx.x * blockDim.x + threadIdx.x;
    if (idx >= ND * KPAD) return;
    int n = idx / KPAD;
    int k = idx - n * KPAD;
    float v = W[(size_t)k * ND + n];
    split2(v, g_Bmsg_h[idx], g_Bmsg_l[idx]);
}

// r,z gate weights: [256 n][256 k] (k<128 -> Wih, k>=128 -> Whh), + summed bias
__global__ void conv_rz(const float* __restrict__ Wih, const float* __restrict__ Whh,
                        const float* __restrict__ bih, const float* __restrict__ bhh) {
    int idx = blockIdx.x * blockDim.x + threadIdx.x;
    if (idx >= 256 * 256) return;
    int n = idx >> 8;
    int k = idx & 255;
    float v = (k < 128) ? Wih[(size_t)k * GD + n] : Whh[(size_t)(k - 128) * GD + n];
    split2(v, g_Brz_h[idx], g_Brz_l[idx]);
    if (idx < 256) g_brz[idx] = bih[idx] + bhh[idx];
}

// n-gate weights: Bin = Wih_n^T, Bwn = Whh_n^T  (each [128 n][128 k])
__global__ void conv_n(const float* __restrict__ Wih, const float* __restrict__ Whh) {
    int idx = blockIdx.x * blockDim.x + threadIdx.x;
    if (idx >= 2 * ND * ND) return;
    int which = idx >> 14;          // 0 -> Bin, 1 -> Bwn
    int r = idx & (ND * ND - 1);
    int n = r >> 7;
    int k = r & 127;
    if (which == 0) {
        float v = Wih[(size_t)k * GD + 256 + n];
        split2(v, g_Bin_h[r], g_Bin_l[r]);
    } else {
        float v = Whh[(size_t)k * GD + 256 + n];
        split2(v, g_Bwn_h[r], g_Bwn_l[r]);
    }
}

// ---------------- gather: X = [S | deg*hv | E] as bf16 splits ----------------
__global__ void gather_kernel(const float* __restrict__ hv, const int* __restrict__ src) {
    int warp = (blockIdx.x * blockDim.x + threadIdx.x) >> 5;
    int lane = threadIdx.x & 31;
    if (warp >= NN) return;
    int v = warp;
    int beg = g_rowptr[v];
    int end = g_rowptr[v + 1];
    float s0 = 0.f, s1 = 0.f, s2 = 0.f, s3 = 0.f;
    for (int i = beg; i < end; i++) {
        int e = g_eidx[i];
        int s = src[e];
        const float* hr = hv + (size_t)s * ND;
        s0 += hr[lane];
        s1 += hr[32 + lane];
        s2 += hr[64 + lane];
        s3 += hr[96 + lane];
    }
    float d = g_degf[v];
    const float* hvr = hv + (size_t)v * ND;
    __nv_bfloat16* xh = g_Xh + (size_t)v * KPAD;
    __nv_bfloat16* xl = g_Xl + (size_t)v * KPAD;
    float vals[9];
    vals[0] = s0; vals[1] = s1; vals[2] = s2; vals[3] = s3;
    vals[4] = d * hvr[lane];
    vals[5] = d * hvr[32 + lane];
    vals[6] = d * hvr[64 + lane];
    vals[7] = d * hvr[96 + lane];
    vals[8] = g_E[(size_t)v * ED + lane];
    #pragma unroll
    for (int s = 0; s < 9; s++)
        split2(vals[s], xh[s * 32 + lane], xl[s * 32 + lane]);
}

// ---------------- cp.async double-buffered HMMA bf16-split GEMM body ---------
#define KC 32
#define STG_BYTES 32768   // 4 tiles x 8KB per stage
#define SMG_BIAS  0
#define SMG_STAGE 1024
#define SMG_TOTAL (1024 + 2 * STG_BYTES)

__device__ __forceinline__
void gemm_body(const __nv_bfloat16* __restrict__ Ah, const __nv_bfloat16* __restrict__ Al,
               int lda,
               const __nv_bfloat16* __restrict__ Bh, const __nv_bfloat16* __restrict__ Bl,
               int ldb,
               const float* __restrict__ bias, const float* __restrict__ rowscale,
               float* __restrict__ Cf, int ldcf,
               __nv_bfloat16* __restrict__ Chi, __nv_bfloat16* __restrict__ Clo, int ldch,
               int M, int K, int blockRow, int blockCol, char* smem) {
    int tid = threadIdx.x, wid = tid >> 5, lane = tid & 31;
    int warpRow = (wid >> 2) * 64;   // 0 / 64
    int warpCol = (wid & 3) * 32;    // 0..96

    float* sBias = (float*)(smem + SMG_BIAS);
    if (tid < 128) sBias[tid] = bias[blockCol + tid];

    uint32_t sstage = smem_u32(smem + SMG_STAGE);

    float acc[4][4][4];
    #pragma unroll
    for (int mt = 0; mt < 4; mt++)
        #pragma unroll
        for (int nt = 0; nt < 4; nt++)
            #pragma unroll
            for (int q = 0; q < 4; q++) acc[mt][nt][q] = 0.f;

    int l0 = tid, l1 = 256 + tid;
    int r0l = l0 >> 2, c0 = (l0 & 3) * 16;
    int r1l = l1 >> 2, c1 = (l1 & 3) * 16;
    int sw0 = (r0l * 64 + c0) ^ (((r0l * 64 + c0) >> 3) & 0x30);
    int sw1 = (r1l * 64 + c1) ^ (((r1l * 64 + c1) >> 3) & 0x30);
    int ga0 = blockRow + r0l; if (ga0 >= M) ga0 = M - 1;
    int ga1 = blockRow + r1l; if (ga1 >= M) ga1 = M - 1;
    int gb0 = blockCol + r0l;
    int gb1 = blockCol + r1l;

    int nchunks = K / KC;

    {
        uint32_t st = sstage;
        cpasync16(st + sw0,          (const char*)(Ah + (size_t)ga0 * lda) + c0);
        cpasync16(st + sw1,          (const char*)(Ah + (size_t)ga1 * lda) + c1);
        cpasync16(st + 8192 + sw0,   (const char*)(Al + (size_t)ga0 * lda) + c0);
        cpasync16(st + 8192 + sw1,   (const char*)(Al + (size_t)ga1 * lda) + c1);
        cpasync16(st + 16384 + sw0,  (const char*)(Bh + (size_t)gb0 * ldb) + c0);
        cpasync16(st + 16384 + sw1,  (const char*)(Bh + (size_t)gb1 * ldb) + c1);
        cpasync16(st + 24576 + sw0,  (const char*)(Bl + (size_t)gb0 * ldb) + c0);
        cpasync16(st + 24576 + sw1,  (const char*)(Bl + (size_t)gb1 * ldb) + c1);
    }
    asm volatile("cp.async.commit_group;" ::: "memory");

    int lrow  = lane & 15;
    uint32_t lhalf = (uint32_t)((lane >> 4) * 16);
    uint32_t rm = (uint32_t)(((lrow >> 1) & 3) << 4);

    for (int kc = 0; kc < nchunks; kc++) {
        if (kc + 1 < nchunks) {
            int k0 = (kc + 1) * KC;
            uint32_t st = sstage + ((kc + 1) & 1) * STG_BYTES;
            cpasync16(st + sw0,          (const char*)(Ah + (size_t)ga0 * lda + k0) + c0);
            cpasync16(st + sw1,          (const char*)(Ah + (size_t)ga1 * lda + k0) + c1);
            cpasync16(st + 8192 + sw0,   (const char*)(Al + (size_t)ga0 * lda + k0) + c0);
            cpasync16(st + 8192 + sw1,   (const char*)(Al + (size_t)ga1 * lda + k0) + c1);
            cpasync16(st + 16384 + sw0,  (const char*)(Bh + (size_t)gb0 * ldb + k0) + c0);
            cpasync16(st + 16384 + sw1,  (const char*)(Bh + (size_t)gb1 * ldb + k0) + c1);
            cpasync16(st + 24576 + sw0,  (const char*)(Bl + (size_t)gb0 * ldb + k0) + c0);
            cpasync16(st + 24576 + sw1,  (const char*)(Bl + (size_t)gb1 * ldb + k0) + c1);
        }
        asm volatile("cp.async.commit_group;" ::: "memory");
        asm volatile("cp.async.wait_group 1;" ::: "memory");
        __syncthreads();

        uint32_t stb = sstage + (kc & 1) * STG_BYTES;
        uint32_t sAH = stb, sAL = stb + 8192, sBH = stb + 16384, sBL = stb + 24576;

        #pragma unroll
        for (int ks = 0; ks < 2; ks++) {
            uint32_t koff = ((uint32_t)(ks * 32) + lhalf) ^ rm;
            uint32_t bfh[4][2], bfl[4][2];
            #pragma unroll
            for (int ng = 0; ng < 2; ng++) {
                uint32_t ro = (uint32_t)(warpCol + ng * 16 + lrow) * 64 + koff;
                uint32_t t[4];
                ldm_x4(t, sBH + ro);
                bfh[ng * 2 + 0][0] = t[0]; bfh[ng * 2 + 1][0] = t[1];
                bfh[ng * 2 + 0][1] = t[2]; bfh[ng * 2 + 1][1] = t[3];
                ldm_x4(t, sBL + ro);
                bfl[ng * 2 + 0][0] = t[0]; bfl[ng * 2 + 1][0] = t[1];
                bfl[ng * 2 + 0][1] = t[2]; bfl[ng * 2 + 1][1] = t[3];
            }
            #pragma unroll
            for (int mt = 0; mt < 4; mt++) {
                uint32_t ro = (uint32_t)(warpRow + mt * 16 + lrow) * 64 + koff;
                uint32_t ah[4], al[4];
                ldm_x4(ah, sAH + ro);
                ldm_x4(al, sAL + ro);
                #pragma unroll
                for (int nt = 0; nt < 4; nt++) {
                    mma_bf16(acc[mt][nt], ah, bfh[nt]);
                    mma_bf16(acc[mt][nt], ah, bfl[nt]);
                    mma_bf16(acc[mt][nt], al, bfh[nt]);
                }
            }
        }
        __syncthreads();
    }

    // ---- epilogue ----
    int rbase = blockRow + warpRow;
    #pragma unroll
    for (int mt = 0; mt < 4; mt++) {
        int r0 = rbase + mt * 16 + (lane >> 2);
        int r1 = r0 + 8;
        float rs0 = 1.f, rs1 = 1.f;
        if (rowscale) {
            if (r0 < M) rs0 = rowscale[r0];
            if (r1 < M) rs1 = rowscale[r1];
        }
        #pragma unroll
        for (int nt = 0; nt < 4; nt++) {
            int col = warpCol + nt * 8 + (lane & 3) * 2;
            float b0 = sBias[col], b1 = sBias[col + 1];
            int gcol = blockCol + col;
            float v00 = acc[mt][nt][0] + rs0 * b0;
            float v01 = acc[mt][nt][1] + rs0 * b1;
            float v10 = acc[mt][nt][2] + rs1 * b0;
            float v11 = acc[mt][nt][3] + rs1 * b1;
            if (Cf) {
                if (r0 < M) *(float2*)(Cf + (size_t)r0 * ldcf + gcol) = make_float2(v00, v01);
                if (r1 < M) *(float2*)(Cf + (size_t)r1 * ldcf + gcol) = make_float2(v10, v11);
            }
            if (Chi) {
                __nv_bfloat16 h0, l0x, h1, l1;
                if (r0 < M) {
                    split2(v00, h0, l0x); split2(v01, h1, l1);
                    *(unsigned*)(Chi + (size_t)r0 * ldch + gcol) =
                        ((unsigned)__bfloat16_as_ushort(h1) << 16) | __bfloat16_as_ushort(h0);
                    *(unsigned*)(Clo + (size_t)r0 * ldch + gcol) =
                        ((unsigned)__bfloat16_as_ushort(l1) << 16) | __bfloat16_as_ushort(l0x);
                }
                if (r1 < M) {
                    split2(v10, h0, l0x); split2(v11, h1, l1);
                    *(unsigned*)(Chi + (size_t)r1 * ldch + gcol) =
                        ((unsigned)__bfloat16_as_ushort(h1) << 16) | __bfloat16_as_ushort(h0);
                    *(unsigned*)(Clo + (size_t)r1 * ldch + gcol) =
                        ((unsigned)__bfloat16_as_ushort(l1) << 16) | __bfloat16_as_ushort(l0x);
                }
            }
        }
    }
}

// msg GEMM: a = X @ Wmsg + deg*b_msg -> cat cols 0-127 (bf16 splits)
__global__ __launch_bounds__(256, 2)
void gemm_msg(const float* __restrict__ bmsg) {
    extern __shared__ char smem[];
    gemm_body(g_Xh, g_Xl, KPAD, g_Bmsg_h, g_Bmsg_l, KPAD,
              bmsg, g_degf,
              (float*)nullptr, 0, g_cath, g_catl, 256,
              NN, KPAD, blockIdx.y * 128, 0, smem);
}

// r,z GEMM: grz = [a|H] @ Brz + (b_ih+b_hh)_rz
__global__ __launch_bounds__(256, 2)
void gemm_rz() {
    extern __shared__ char smem[];
    gemm_body(g_cath, g_catl, 256, g_Brz_h, g_Brz_l, 256,
              g_brz, (const float*)nullptr,
              g_grz, 256, (__nv_bfloat16*)nullptr, (__nv_bfloat16*)nullptr, 0,
              NN, 256, blockIdx.y * 128, blockIdx.x * 128, smem);
}

// n-gate pair: blockIdx.x==0 -> in_ = a@Wih_n + b_ih_n ; ==1 -> hn = H@Whh_n + b_hh_n
__global__ __launch_bounds__(256, 2)
void gemm_npair(const float* __restrict__ bihn, const float* __restrict__ bhhn) {
    extern __shared__ char smem[];
    if (blockIdx.x == 0) {
        gemm_body(g_cath, g_catl, 256, g_Bin_h, g_Bin_l, ND,
                  bihn, (const float*)nullptr,
                  g_in, ND, (__nv_bfloat16*)nullptr, (__nv_bfloat16*)nullptr, 0,
                  NN, ND, blockIdx.y * 128, 0, smem);
    } else {
        gemm_body(g_cath + 128, g_catl + 128, 256, g_Bwn_h, g_Bwn_l, ND,
                  bhhn, (const float*)nullptr,
                  g_hn, ND, (__nv_bfloat16*)nullptr, (__nv_bfloat16*)nullptr, 0,
                  NN, ND, blockIdx.y * 128, 0, smem);
    }
}

// ---------------- GRU elementwise --------------------------------------------
__global__ void gru_kernel(float* __restrict__ hv) {
    int idx = blockIdx.x * blockDim.x + threadIdx.x;
    if (idx >= NN * ND) return;
    int v = idx / ND;
    int j = idx - v * ND;
    float grv = g_grz[(size_t)v * 256 + j];
    float gzv = g_grz[(size_t)v * 256 + 128 + j];
    float inv = g_in[(size_t)v * ND + j];
    float hnv = g_hn[(size_t)v * ND + j];
    float r = 1.0f / (1.0f + expf(-grv));
    float z = 1.0f / (1.0f + expf(-gzv));
    float n = tanhf(inv + r * hnv);
    float h = hv[idx];
    float o = (1.0f - z) * n + z * h;
    hv[idx] = o;
    split2(o, g_cath[(size_t)v * 256 + 128 + j], g_catl[(size_t)v * 256 + 128 + j]);
}

// ---------------- launch -----------------------------------------------------
extern "C" void kernel_launch(void* const* d_in, const int* in_sizes, int n_in,
                              void* d_out, int out_size) {
    const float* hv    = (const float*)d_in[0];
    const float* he    = (const float*)d_in[1];
    const int*   src   = (const int*)d_in[2];
    const int*   dst   = (const int*)d_in[3];
    const float* W_msg = (const float*)d_in[4];
    const float* b_msg = (const float*)d_in[5];
    const float* W_ih  = (const float*)d_in[6];
    const float* W_hh  = (const float*)d_in[7];
    const float* b_ih  = (const float*)d_in[8];
    const float* b_hh  = (const float*)d_in[9];
    float* H = (float*)d_out;

    static int attr_done = 0;
    if (!attr_done) {
        cudaFuncSetAttribute(gemm_msg,   cudaFuncAttributeMaxDynamicSharedMemorySize, SMG_TOTAL);
        cudaFuncSetAttribute(gemm_rz,    cudaFuncAttributeMaxDynamicSharedMemorySize, SMG_TOTAL);
        cudaFuncSetAttribute(gemm_npair, cudaFuncAttributeMaxDynamicSharedMemorySize, SMG_TOTAL);
        attr_done = 1;
    }

    copy_split_kernel<<<(NN * ND + 255) / 256, 256>>>(hv, H, NN * ND);
    zero_cnt<<<(NN + 255) / 256, 256>>>();
    count_kernel<<<(NE + 255) / 256, 256>>>(dst);
    scan1<<<NSCANBLK, SCAN_BLK>>>();
    scan2<<<1, 64>>>();
    scan3<<<(NN + 255) / 256, 256>>>();
    fill_kernel<<<(NE + 255) / 256, 256>>>(dst);
    esum_kernel<<<(NN * 32 + 255) / 256, 256>>>(he);

    int mtiles = (NN + 127) / 128;   // 391

    for (int t = 0; t < NROUNDS; t++) {
        conv_wmsg<<<(ND * KPAD + 255) / 256, 256>>>(W_msg + (size_t)t * CATD * ND);
        conv_rz<<<(256 * 256 + 255) / 256, 256>>>(W_ih + (size_t)t * ND * GD,
                                                  W_hh + (size_t)t * ND * GD,
                                                  b_ih + (size_t)t * GD,
                                                  b_hh + (size_t)t * GD);
        conv_n<<<(2 * ND * ND + 255) / 256, 256>>>(W_ih + (size_t)t * ND * GD,
                                                   W_hh + (size_t)t * ND * GD);

        gather_kernel<<<(NN * 32 + 255) / 256, 256>>>(H, src);

        gemm_msg<<<dim3(1, mtiles), 256, SMG_TOTAL>>>(b_msg + (size_t)t * ND);
        gemm_rz<<<dim3(2, mtiles), 256, SMG_TOTAL>>>();
        gemm_npair<<<dim3(2, mtiles), 256, SMG_TOTAL>>>(b_ih + (size_t)t * GD + 256,
                                                        b_hh + (size_t)t * GD + 256);

        gru_kernel<<<(NN * ND + 255) / 256, 256>>>(H);
    }
}

// round 11
// speedup vs baseline: 2.0244x; 1.1667x over previous
#include <cuda_runtime.h>
#include <cuda_fp16.h>
#include <math.h>
#include <stdint.h>

// Problem constants
#define NN      50000
#define NE      800000
#define ND      128
#define ED      32
#define CATD    288
#define KPAD    288     // divisible by KC=32
#define GD      384     // 3*ND
#define NROUNDS 2

#define SCAN_BLK 1024
#define NSCANBLK ((NN + SCAN_BLK - 1) / SCAN_BLK)   // 49

// ---------------- device scratch -------------------------------------------
__device__ int   g_cnt[NN];
__device__ int   g_rowptr[NN + 1];
__device__ int   g_cursor[NN];
__device__ float g_degf[NN];
__device__ int   g_bsum[64];
__device__ int   g_boffs[64];
__device__ int   g_eidx[NE];
__device__ float g_E[(size_t)NN * ED];          // per-node edge-feature sum (round-invariant)

__device__ __half g_Xh[(size_t)NN * KPAD];      // A-split hi of X
__device__ __half g_Xl[(size_t)NN * KPAD];      // A-split lo of X
// cat = [a (cols 0-127) | H (cols 128-255)] fp16 hi/lo
__device__ __half g_cath[(size_t)NN * 256];
__device__ __half g_catl[(size_t)NN * 256];
__device__ float g_grz[(size_t)NN * 256];
__device__ float g_in[(size_t)NN * ND];
__device__ float g_hn[(size_t)NN * ND];

// weights (per round, rebuilt) — single fp16 (B-side rounding ~2^-12 only)
__device__ __half g_Bmsg[ND * KPAD];
__device__ __half g_Brz[256 * 256];   // stacked [Wih;Whh] r,z gates, transposed
__device__ __half g_Bin[ND * ND];     // Wih_n transposed
__device__ __half g_Bwn[ND * ND];     // Whh_n transposed
__device__ float g_brz[256];          // b_ih + b_hh (r,z gates)

// ---------------- small helpers --------------------------------------------
__device__ __forceinline__ void split2h(float x, __half& h, __half& l) {
    h = __float2half_rn(x);
    l = __float2half_rn(x - __half2float(h));
}

__device__ __forceinline__ uint32_t smem_u32(const void* p) {
    uint32_t a;
    asm("{ .reg .u64 t; cvta.to.shared.u64 t, %1; cvt.u32.u64 %0, t; }" : "=r"(a) : "l"(p));
    return a;
}

__device__ __forceinline__ void ldm_x4(uint32_t* r, uint32_t addr) {
    asm volatile("ldmatrix.sync.aligned.m8n8.x4.shared.b16 {%0,%1,%2,%3}, [%4];"
        : "=r"(r[0]), "=r"(r[1]), "=r"(r[2]), "=r"(r[3]) : "r"(addr));
}

__device__ __forceinline__ void mma_f16(float* c, const uint32_t* a, const uint32_t* b) {
    asm volatile(
        "mma.sync.aligned.m16n8k16.row.col.f32.f16.f16.f32 "
        "{%0,%1,%2,%3}, {%4,%5,%6,%7}, {%8,%9}, {%0,%1,%2,%3};"
        : "+f"(c[0]), "+f"(c[1]), "+f"(c[2]), "+f"(c[3])
        : "r"(a[0]), "r"(a[1]), "r"(a[2]), "r"(a[3]), "r"(b[0]), "r"(b[1]));
}

__device__ __forceinline__ void cpasync16(uint32_t saddr, const void* gptr) {
    asm volatile("cp.async.cg.shared.global [%0], [%1], 16;"
                 :: "r"(saddr), "l"(gptr));
}

// ---------------- init / CSR kernels ----------------------------------------
__global__ void copy_split_kernel(const float* __restrict__ src, float* __restrict__ dst,
                                  int n) {
    int i = blockIdx.x * blockDim.x + threadIdx.x;
    if (i < n) {
        float v = src[i];
        dst[i] = v;
        int vv = i / ND, j = i - vv * ND;
        split2h(v, g_cath[(size_t)vv * 256 + 128 + j], g_catl[(size_t)vv * 256 + 128 + j]);
    }
}

__global__ void zero_cnt() {
    int i = blockIdx.x * blockDim.x + threadIdx.x;
    if (i < NN) g_cnt[i] = 0;
}

__global__ void count_kernel(const int* __restrict__ dst) {
    int e = blockIdx.x * blockDim.x + threadIdx.x;
    if (e < NE) atomicAdd(&g_cnt[dst[e]], 1);
}

__global__ void scan1() {
    __shared__ int buf[SCAN_BLK];
    int tid = threadIdx.x;
    int i = blockIdx.x * SCAN_BLK + tid;
    buf[tid] = (i < NN) ? g_cnt[i] : 0;
    __syncthreads();
    #pragma unroll
    for (int off = 1; off < SCAN_BLK; off <<= 1) {
        int t = (tid >= off) ? buf[tid - off] : 0;
        __syncthreads();
        buf[tid] += t;
        __syncthreads();
    }
    if (i < NN) g_rowptr[1 + i] = buf[tid];
    if (tid == SCAN_BLK - 1) g_bsum[blockIdx.x] = buf[tid];
}

__global__ void scan2() {
    __shared__ int buf[64];
    int tid = threadIdx.x;
    int own = (tid < NSCANBLK) ? g_bsum[tid] : 0;
    buf[tid] = own;
    __syncthreads();
    #pragma unroll
    for (int off = 1; off < 64; off <<= 1) {
        int t = (tid >= off) ? buf[tid - off] : 0;
        __syncthreads();
        buf[tid] += t;
        __syncthreads();
    }
    if (tid < NSCANBLK) g_boffs[tid] = buf[tid] - own;
}

__global__ void scan3() {
    int i = blockIdx.x * blockDim.x + threadIdx.x;
    if (i >= NN) return;
    int b = i / SCAN_BLK;
    int incl = g_rowptr[1 + i] + g_boffs[b];
    g_rowptr[1 + i] = incl;
    int c = g_cnt[i];
    g_cursor[i] = incl - c;
    g_degf[i]   = (float)c;
    if (i == 0) g_rowptr[0] = 0;
}

__global__ void fill_kernel(const int* __restrict__ dst) {
    int e = blockIdx.x * blockDim.x + threadIdx.x;
    if (e < NE) {
        int d = dst[e];
        int p = atomicAdd(&g_cursor[d], 1);
        g_eidx[p] = e;
    }
}

// per-node edge-feature sum (once; invariant across rounds)
__global__ void esum_kernel(const float* __restrict__ he) {
    int warp = (blockIdx.x * blockDim.x + threadIdx.x) >> 5;
    int lane = threadIdx.x & 31;
    if (warp >= NN) return;
    int beg = g_rowptr[warp], end = g_rowptr[warp + 1];
    float se = 0.f;
    for (int i = beg; i < end; i++)
        se += he[(size_t)g_eidx[i] * ED + lane];
    g_E[(size_t)warp * ED + lane] = se;
}

// ---------------- weight transpose (single fp16) -----------------------------
__global__ void conv_wmsg(const float* __restrict__ W) {
    int idx = blockIdx.x * blockDim.x + threadIdx.x;
    if (idx >= ND * KPAD) return;
    int n = idx / KPAD;
    int k = idx - n * KPAD;
    g_Bmsg[idx] = __float2half_rn(W[(size_t)k * ND + n]);
}

// r,z gate weights: [256 n][256 k] (k<128 -> Wih, k>=128 -> Whh), + summed bias
__global__ void conv_rz(const float* __restrict__ Wih, const float* __restrict__ Whh,
                        const float* __restrict__ bih, const float* __restrict__ bhh) {
    int idx = blockIdx.x * blockDim.x + threadIdx.x;
    if (idx >= 256 * 256) return;
    int n = idx >> 8;
    int k = idx & 255;
    float v = (k < 128) ? Wih[(size_t)k * GD + n] : Whh[(size_t)(k - 128) * GD + n];
    g_Brz[idx] = __float2half_rn(v);
    if (idx < 256) g_brz[idx] = bih[idx] + bhh[idx];
}

// n-gate weights: Bin = Wih_n^T, Bwn = Whh_n^T  (each [128 n][128 k])
__global__ void conv_n(const float* __restrict__ Wih, const float* __restrict__ Whh) {
    int idx = blockIdx.x * blockDim.x + threadIdx.x;
    if (idx >= 2 * ND * ND) return;
    int which = idx >> 14;          // 0 -> Bin, 1 -> Bwn
    int r = idx & (ND * ND - 1);
    int n = r >> 7;
    int k = r & 127;
    if (which == 0)
        g_Bin[r] = __float2half_rn(Wih[(size_t)k * GD + 256 + n]);
    else
        g_Bwn[r] = __float2half_rn(Whh[(size_t)k * GD + 256 + n]);
}

// ---------------- gather: X = [S | deg*hv | E] as fp16 splits ----------------
__global__ void gather_kernel(const float* __restrict__ hv, const int* __restrict__ src) {
    int warp = (blockIdx.x * blockDim.x + threadIdx.x) >> 5;
    int lane = threadIdx.x & 31;
    if (warp >= NN) return;
    int v = warp;
    int beg = g_rowptr[v];
    int end = g_rowptr[v + 1];
    float s0 = 0.f, s1 = 0.f, s2 = 0.f, s3 = 0.f;
    for (int i = beg; i < end; i++) {
        int e = g_eidx[i];
        int s = src[e];
        const float* hr = hv + (size_t)s * ND;
        s0 += hr[lane];
        s1 += hr[32 + lane];
        s2 += hr[64 + lane];
        s3 += hr[96 + lane];
    }
    float d = g_degf[v];
    const float* hvr = hv + (size_t)v * ND;
    __half* xh = g_Xh + (size_t)v * KPAD;
    __half* xl = g_Xl + (size_t)v * KPAD;
    float vals[9];
    vals[0] = s0; vals[1] = s1; vals[2] = s2; vals[3] = s3;
    vals[4] = d * hvr[lane];
    vals[5] = d * hvr[32 + lane];
    vals[6] = d * hvr[64 + lane];
    vals[7] = d * hvr[96 + lane];
    vals[8] = g_E[(size_t)v * ED + lane];
    #pragma unroll
    for (int s = 0; s < 9; s++)
        split2h(vals[s], xh[s * 32 + lane], xl[s * 32 + lane]);
}

// ---------------- cp.async 3-stage HMMA fp16 A-split GEMM body ---------------
// C[M, ...] = (Ah+Al)[M,K] @ B^T  (B stored [Ncols][K], K-major fp16)
//   + rowscale*bias.  128x128 CTA tile, 8 warps, K chunk 32, 3 smem stages.
// 2 MMA passes: Ah@B + Al@B, fp32 accumulate.
#define KC 32
#define STG_BYTES 24576   // 3 tiles (Ah, Al, B) x 8KB per stage
#define NSTG 3
#define SMG_BIAS  0
#define SMG_STAGE 1024
#define SMG_TOTAL (1024 + NSTG * STG_BYTES)   // 74752

__device__ __forceinline__
void gemm_body(const __half* __restrict__ Ah, const __half* __restrict__ Al,
               int lda,
               const __half* __restrict__ B, int ldb,
               const float* __restrict__ bias, const float* __restrict__ rowscale,
               float* __restrict__ Cf, int ldcf,
               __half* __restrict__ Chi, __half* __restrict__ Clo, int ldch,
               int M, int K, int blockRow, int blockCol, char* smem) {
    int tid = threadIdx.x, wid = tid >> 5, lane = tid & 31;
    int warpRow = (wid >> 2) * 64;   // 0 / 64
    int warpCol = (wid & 3) * 32;    // 0..96

    float* sBias = (float*)(smem + SMG_BIAS);
    if (tid < 128) sBias[tid] = bias[blockCol + tid];

    uint32_t sstage = smem_u32(smem + SMG_STAGE);

    float acc[4][4][4];
    #pragma unroll
    for (int mt = 0; mt < 4; mt++)
        #pragma unroll
        for (int nt = 0; nt < 4; nt++)
            #pragma unroll
            for (int q = 0; q < 4; q++) acc[mt][nt][q] = 0.f;

    // per-thread load mapping: 2 x 16B vecs per tile (128 rows x 64B rows)
    int l0 = tid, l1 = 256 + tid;
    int r0l = l0 >> 2, c0 = (l0 & 3) * 16;
    int r1l = l1 >> 2, c1 = (l1 & 3) * 16;
    int sw0 = (r0l * 64 + c0) ^ (((r0l * 64 + c0) >> 3) & 0x30);
    int sw1 = (r1l * 64 + c1) ^ (((r1l * 64 + c1) >> 3) & 0x30);
    int ga0 = blockRow + r0l; if (ga0 >= M) ga0 = M - 1;
    int ga1 = blockRow + r1l; if (ga1 >= M) ga1 = M - 1;
    int gb0 = blockCol + r0l;
    int gb1 = blockCol + r1l;

    int nchunks = K / KC;

    // prologue: prefetch chunks 0 and 1 (nchunks >= 4 always here)
    #pragma unroll
    for (int p = 0; p < 2; p++) {
        int k0 = p * KC;
        uint32_t st = sstage + p * STG_BYTES;
        cpasync16(st + sw0,          (const char*)(Ah + (size_t)ga0 * lda + k0) + c0);
        cpasync16(st + sw1,          (const char*)(Ah + (size_t)ga1 * lda + k0) + c1);
        cpasync16(st + 8192 + sw0,   (const char*)(Al + (size_t)ga0 * lda + k0) + c0);
        cpasync16(st + 8192 + sw1,   (const char*)(Al + (size_t)ga1 * lda + k0) + c1);
        cpasync16(st + 16384 + sw0,  (const char*)(B + (size_t)gb0 * ldb + k0) + c0);
        cpasync16(st + 16384 + sw1,  (const char*)(B + (size_t)gb1 * ldb + k0) + c1);
        asm volatile("cp.async.commit_group;" ::: "memory");
    }

    int lrow  = lane & 15;
    uint32_t lhalf = (uint32_t)((lane >> 4) * 16);
    uint32_t rm = (uint32_t)(((lrow >> 1) & 3) << 4);

    int stage = 0;
    for (int kc = 0; kc < nchunks; kc++) {
        // wait for chunk kc (newest 1 group may still fly), sync all warps
        asm volatile("cp.async.wait_group 1;" ::: "memory");
        __syncthreads();

        // prefetch chunk kc+2 into stage (kc+2)%3 (safe: sync above guarantees
        // all warps finished computing chunk kc-1, which used this stage)
        if (kc + 2 < nchunks) {
            int k0 = (kc + 2) * KC;
            int s2 = stage + 2; if (s2 >= NSTG) s2 -= NSTG;
            uint32_t st = sstage + s2 * STG_BYTES;
            cpasync16(st + sw0,          (const char*)(Ah + (size_t)ga0 * lda + k0) + c0);
            cpasync16(st + sw1,          (const char*)(Ah + (size_t)ga1 * lda + k0) + c1);
            cpasync16(st + 8192 + sw0,   (const char*)(Al + (size_t)ga0 * lda + k0) + c0);
            cpasync16(st + 8192 + sw1,   (const char*)(Al + (size_t)ga1 * lda + k0) + c1);
            cpasync16(st + 16384 + sw0,  (const char*)(B + (size_t)gb0 * ldb + k0) + c0);
            cpasync16(st + 16384 + sw1,  (const char*)(B + (size_t)gb1 * ldb + k0) + c1);
        }
        asm volatile("cp.async.commit_group;" ::: "memory");

        uint32_t stb = sstage + stage * STG_BYTES;
        uint32_t sAH = stb, sAL = stb + 8192, sB = stb + 16384;

        #pragma unroll
        for (int ks = 0; ks < 2; ks++) {
            uint32_t koff = ((uint32_t)(ks * 32) + lhalf) ^ rm;
            uint32_t bf[4][2];
            #pragma unroll
            for (int ng = 0; ng < 2; ng++) {
                uint32_t ro = (uint32_t)(warpCol + ng * 16 + lrow) * 64 + koff;
                uint32_t t[4];
                ldm_x4(t, sB + ro);
                bf[ng * 2 + 0][0] = t[0]; bf[ng * 2 + 1][0] = t[1];
                bf[ng * 2 + 0][1] = t[2]; bf[ng * 2 + 1][1] = t[3];
            }
            #pragma unroll
            for (int mt = 0; mt < 4; mt++) {
                uint32_t ro = (uint32_t)(warpRow + mt * 16 + lrow) * 64 + koff;
                uint32_t ah[4], al[4];
                ldm_x4(ah, sAH + ro);
                ldm_x4(al, sAL + ro);
                #pragma unroll
                for (int nt = 0; nt < 4; nt++) {
                    mma_f16(acc[mt][nt], ah, bf[nt]);
                    mma_f16(acc[mt][nt], al, bf[nt]);
                }
            }
        }
        stage++; if (stage >= NSTG) stage = 0;
    }

    // ---- epilogue ----
    int rbase = blockRow + warpRow;
    #pragma unroll
    for (int mt = 0; mt < 4; mt++) {
        int r0 = rbase + mt * 16 + (lane >> 2);
        int r1 = r0 + 8;
        float rs0 = 1.f, rs1 = 1.f;
        if (rowscale) {
            if (r0 < M) rs0 = rowscale[r0];
            if (r1 < M) rs1 = rowscale[r1];
        }
        #pragma unroll
        for (int nt = 0; nt < 4; nt++) {
            int col = warpCol + nt * 8 + (lane & 3) * 2;
            float b0 = sBias[col], b1 = sBias[col + 1];
            int gcol = blockCol + col;
            float v00 = acc[mt][nt][0] + rs0 * b0;
            float v01 = acc[mt][nt][1] + rs0 * b1;
            float v10 = acc[mt][nt][2] + rs1 * b0;
            float v11 = acc[mt][nt][3] + rs1 * b1;
            if (Cf) {
                if (r0 < M) *(float2*)(Cf + (size_t)r0 * ldcf + gcol) = make_float2(v00, v01);
                if (r1 < M) *(float2*)(Cf + (size_t)r1 * ldcf + gcol) = make_float2(v10, v11);
            }
            if (Chi) {
                __half h0, l0x, h1, l1;
                if (r0 < M) {
                    split2h(v00, h0, l0x); split2h(v01, h1, l1);
                    *(unsigned*)(Chi + (size_t)r0 * ldch + gcol) =
                        ((unsigned)__half_as_ushort(h1) << 16) | __half_as_ushort(h0);
                    *(unsigned*)(Clo + (size_t)r0 * ldch + gcol) =
                        ((unsigned)__half_as_ushort(l1) << 16) | __half_as_ushort(l0x);
                }
                if (r1 < M) {
                    split2h(v10, h0, l0x); split2h(v11, h1, l1);
                    *(unsigned*)(Chi + (size_t)r1 * ldch + gcol) =
                        ((unsigned)__half_as_ushort(h1) << 16) | __half_as_ushort(h0);
                    *(unsigned*)(Clo + (size_t)r1 * ldch + gcol) =
                        ((unsigned)__half_as_ushort(l1) << 16) | __half_as_ushort(l0x);
                }
            }
        }
    }
}

// msg GEMM: a = X @ Wmsg + deg*b_msg -> cat cols 0-127 (fp16 splits)
__global__ __launch_bounds__(256, 2)
void gemm_msg(const float* __restrict__ bmsg) {
    extern __shared__ char smem[];
    gemm_body(g_Xh, g_Xl, KPAD, g_Bmsg, KPAD,
              bmsg, g_degf,
              (float*)nullptr, 0, g_cath, g_catl, 256,
              NN, KPAD, blockIdx.y * 128, 0, smem);
}

// merged gate GEMMs: x=0,1 -> grz cols; x=2 -> in_ = a@Wih_n; x=3 -> hn = H@Whh_n
__global__ __launch_bounds__(256, 2)
void gemm_gates(const float* __restrict__ bihn, const float* __restrict__ bhhn) {
    extern __shared__ char smem[];
    int bx = blockIdx.x;
    if (bx < 2) {
        gemm_body(g_cath, g_catl, 256, g_Brz, 256,
                  g_brz, (const float*)nullptr,
                  g_grz, 256, (__half*)nullptr, (__half*)nullptr, 0,
                  NN, 256, blockIdx.y * 128, bx * 128, smem);
    } else if (bx == 2) {
        gemm_body(g_cath, g_catl, 256, g_Bin, ND,
                  bihn, (const float*)nullptr,
                  g_in, ND, (__half*)nullptr, (__half*)nullptr, 0,
                  NN, ND, blockIdx.y * 128, 0, smem);
    } else {
        gemm_body(g_cath + 128, g_catl + 128, 256, g_Bwn, ND,
                  bhhn, (const float*)nullptr,
                  g_hn, ND, (__half*)nullptr, (__half*)nullptr, 0,
                  NN, ND, blockIdx.y * 128, 0, smem);
    }
}

// ---------------- GRU elementwise --------------------------------------------
__global__ void gru_kernel(float* __restrict__ hv) {
    int idx = blockIdx.x * blockDim.x + threadIdx.x;
    if (idx >= NN * ND) return;
    int v = idx / ND;
    int j = idx - v * ND;
    float grv = g_grz[(size_t)v * 256 + j];
    float gzv = g_grz[(size_t)v * 256 + 128 + j];
    float inv = g_in[(size_t)v * ND + j];
    float hnv = g_hn[(size_t)v * ND + j];
    float r = 1.0f / (1.0f + expf(-grv));
    float z = 1.0f / (1.0f + expf(-gzv));
    float n = tanhf(inv + r * hnv);
    float h = hv[idx];
    float o = (1.0f - z) * n + z * h;
    hv[idx] = o;
    split2h(o, g_cath[(size_t)v * 256 + 128 + j], g_catl[(size_t)v * 256 + 128 + j]);
}

// ---------------- launch -----------------------------------------------------
extern "C" void kernel_launch(void* const* d_in, const int* in_sizes, int n_in,
                              void* d_out, int out_size) {
    const float* hv    = (const float*)d_in[0];
    const float* he    = (const float*)d_in[1];
    const int*   src   = (const int*)d_in[2];
    const int*   dst   = (const int*)d_in[3];
    const float* W_msg = (const float*)d_in[4];
    const float* b_msg = (const float*)d_in[5];
    const float* W_ih  = (const float*)d_in[6];
    const float* W_hh  = (const float*)d_in[7];
    const float* b_ih  = (const float*)d_in[8];
    const float* b_hh  = (const float*)d_in[9];
    float* H = (float*)d_out;

    static int attr_done = 0;
    if (!attr_done) {
        cudaFuncSetAttribute(gemm_msg,   cudaFuncAttributeMaxDynamicSharedMemorySize, SMG_TOTAL);
        cudaFuncSetAttribute(gemm_gates, cudaFuncAttributeMaxDynamicSharedMemorySize, SMG_TOTAL);
        attr_done = 1;
    }

    copy_split_kernel<<<(NN * ND + 255) / 256, 256>>>(hv, H, NN * ND);
    zero_cnt<<<(NN + 255) / 256, 256>>>();
    count_kernel<<<(NE + 255) / 256, 256>>>(dst);
    scan1<<<NSCANBLK, SCAN_BLK>>>();
    scan2<<<1, 64>>>();
    scan3<<<(NN + 255) / 256, 256>>>();
    fill_kernel<<<(NE + 255) / 256, 256>>>(dst);
    esum_kernel<<<(NN * 32 + 255) / 256, 256>>>(he);

    int mtiles = (NN + 127) / 128;   // 391

    for (int t = 0; t < NROUNDS; t++) {
        conv_wmsg<<<(ND * KPAD + 255) / 256, 256>>>(W_msg + (size_t)t * CATD * ND);
        conv_rz<<<(256 * 256 + 255) / 256, 256>>>(W_ih + (size_t)t * ND * GD,
                                                  W_hh + (size_t)t * ND * GD,
                                                  b_ih + (size_t)t * GD,
                                                  b_hh + (size_t)t * GD);
        conv_n<<<(2 * ND * ND + 255) / 256, 256>>>(W_ih + (size_t)t * ND * GD,
                                                   W_hh + (size_t)t * ND * GD);

        gather_kernel<<<(NN * 32 + 255) / 256, 256>>>(H, src);

        gemm_msg<<<dim3(1, mtiles), 256, SMG_TOTAL>>>(b_msg + (size_t)t * ND);
        gemm_gates<<<dim3(4, mtiles), 256, SMG_TOTAL>>>(b_ih + (size_t)t * GD + 256,
                                                        b_hh + (size_t)t * GD + 256);

        gru_kernel<<<(NN * ND + 255) / 256, 256>>>(H);
    }
}